// round 11
// baseline (speedup 1.0000x reference)
#include <cuda_runtime.h>

// Problem constants
constexpr int B_ = 8, L_ = 12, C_ = 4096, O_ = 128, N_ = 4224;
constexpr int E_ = 64, A_ = 64, H_ = 256;
constexpr int DCOLS = 80;  // X cols: 0..63 tIn, 64..75 proj_s, 76 = ones, 77..79 pad

// ---------------- scratch (device globals) ----------------------------------
__device__ __align__(16) float g_objIn[B_ * O_ * E_];
__device__ __align__(16) float g_objOut[B_ * O_ * E_];
__device__ __align__(16) float g_T1c[C_ * H_];
__device__ __align__(16) float g_T1o[B_ * O_ * H_];
__device__ __align__(16) float g_meta[B_ * L_ * A_];
__device__ __align__(16) float g_arg[B_ * L_ * E_];
__device__ __align__(16) float g_proj[B_ * N_ * 16];
__device__ __align__(16) float g_psum[B_ * 16];
__device__ __align__(16) float g_tInsum[B_ * E_];
__device__ __align__(16) float g_D[B_ * L_ * H_ * DCOLS];   // [bt][h][c]
__device__ __align__(16) float g_E[B_ * L_ * DCOLS * 64];   // [bt][c][e'] (transposed)
__device__ __align__(16) float g_Msum[B_ * E_ * A_];
__device__ __align__(16) float g_ol[B_ * N_];
__device__ int g_olmax[B_];

__device__ __forceinline__ unsigned long long pack2(float v) {
    unsigned int b = __float_as_uint(v);
    return ((unsigned long long)b << 32) | b;
}
__device__ __forceinline__ float lo2(unsigned long long v) {
    return __uint_as_float((unsigned)(v & 0xffffffffULL));
}
__device__ __forceinline__ float hi2(unsigned long long v) {
    return __uint_as_float((unsigned)(v >> 32));
}

// ---------------- 1: fused precompute: T1c | objT1o | zero | arg gather -------
// blocks: [0,256) T1c, [256,320) objT1o, [320,344) zero, [344] arg gather
__global__ void __launch_bounds__(256) k_pre(
    const float* __restrict__ clsIn, const float* __restrict__ clsOut,
    const float* __restrict__ atIn, const float* __restrict__ atOut,
    const int* __restrict__ gt_cls, const int* __restrict__ gt_attr,
    const float* __restrict__ w1, const float* __restrict__ cOut,
    const int* __restrict__ args) {
    int bx = blockIdx.x;
    int tid = threadIdx.x;
    __shared__ float s_emb[1024];
    __shared__ float s_w[4096];

    if (bx < 256) {
        int n0 = bx * 16;
        for (int i = tid; i < 1024; i += 256) s_emb[i] = cOut[n0 * E_ + i];
        float acc[16];
#pragma unroll
        for (int r = 0; r < 16; r++) acc[r] = 0.f;
        for (int ch = 0; ch < 4; ch++) {
            __syncthreads();
            {
                const float4* src = (const float4*)(w1 + ch * 16 * H_);
                float4* dst = (float4*)s_w;
                for (int i = tid; i < 1024; i += 256) dst[i] = src[i];
            }
            __syncthreads();
#pragma unroll
            for (int e = 0; e < 16; e++) {
                float w = s_w[e * H_ + tid];
                int ge = ch * 16 + e;
#pragma unroll
                for (int r = 0; r < 16; r++) acc[r] += s_emb[r * 64 + ge] * w;
            }
        }
#pragma unroll
        for (int r = 0; r < 16; r++) g_T1c[(n0 + r) * H_ + tid] = acc[r];
    } else if (bx < 320) {
        int idx = bx - 256;
        int b = idx >> 3;
        int o0 = (idx & 7) * 16;
        for (int i = tid; i < 1024; i += 256) {
            int r = i >> 6, e = i & 63;
            int o = o0 + r;
            int cls = gt_cls[b * O_ + o];
            float vi = clsIn[cls * E_ + e];
            float vo = clsOut[cls * E_ + e];
#pragma unroll
            for (int k = 0; k < 8; k++) {
                int at = gt_attr[(b * O_ + o) * 8 + k];
                vi += atIn[at * E_ + e];
                vo += atOut[at * E_ + e];
            }
            g_objIn[(b * O_ + o) * E_ + e] = vi;
            g_objOut[(b * O_ + o) * E_ + e] = vo;
            s_emb[i] = vo;
        }
        float acc[16];
#pragma unroll
        for (int r = 0; r < 16; r++) acc[r] = 0.f;
        for (int ch = 0; ch < 4; ch++) {
            __syncthreads();
            {
                const float4* src = (const float4*)(w1 + ch * 16 * H_);
                float4* dst = (float4*)s_w;
                for (int i = tid; i < 1024; i += 256) dst[i] = src[i];
            }
            __syncthreads();
#pragma unroll
            for (int e = 0; e < 16; e++) {
                float w = s_w[e * H_ + tid];
                int ge = ch * 16 + e;
#pragma unroll
                for (int r = 0; r < 16; r++) acc[r] += s_emb[r * 64 + ge] * w;
            }
        }
#pragma unroll
        for (int r = 0; r < 16; r++) g_T1o[(b * O_ + o0 + r) * H_ + tid] = acc[r];
    } else if (bx < 344) {
        int i = (bx - 320) * 256 + tid;   // 0..6143
        float4 z = make_float4(0.f, 0.f, 0.f, 0.f);
        float4* d4 = (float4*)g_D;
#pragma unroll
        for (int j = 0; j < 80; j++) d4[j * 6144 + i] = z;
        if (bx == 320) {
            if (tid < 128) g_psum[tid] = 0.f;
            g_tInsum[tid] = 0.f;
            g_tInsum[256 + tid] = 0.f;
            if (tid < 8) g_olmax[tid] = 0;
        }
    } else {
        for (int i = tid; i < B_ * L_ * E_; i += 256) {
            int bt = i >> 6, e = i & 63;
            g_arg[i] = cOut[args[bt] * E_ + e];
        }
    }
}

// ---------------- 2: meta recurrence (512 threads, split-K) -------------------
__global__ void __launch_bounds__(512) k_meta(
    const float* __restrict__ meta_init,
    const float* __restrict__ mw1, const float* __restrict__ mb1,
    const float* __restrict__ mw2, const float* __restrict__ mb2,
    const int* __restrict__ ops) {
    extern __shared__ float dsm[];
    float* s_w1 = dsm;             // 128*256 (full meta_w1)
    float* s_w2 = dsm + 32768;     // 256*64
    __shared__ float s_in[128];    // [meta(64) | arg(64)]
    __shared__ float s_h[256], s_pre[512], s_part[512];
    int b = blockIdx.x;
    int tid = threadIdx.x;
    {
        const float4* w1_4 = (const float4*)mw1;
        float4* d1 = (float4*)s_w1;
        for (int i = tid; i < 8192; i += 512) d1[i] = w1_4[i];
        const float4* w2_4 = (const float4*)mw2;
        float4* d2 = (float4*)s_w2;
        for (int i = tid; i < 4096; i += 512) d2[i] = w2_4[i];
    }
    float r_mb1 = (tid < 256) ? mb1[tid] : 0.f;
    float r_mb2 = (tid < 64) ? mb2[tid] : 0.f;
    if (tid < 64) s_in[tid] = meta_init[tid];
    __syncthreads();
    int h = tid & 255, half = tid >> 8;
    int a = tid & 63, pq = tid >> 6;
    for (int t = 0; t < L_; t++) {
        if (tid < 64) s_in[64 + tid] = g_arg[(b * L_ + t) * E_ + tid];
        __syncthreads();
        {
            int base = half * 64;
            float p0 = 0.f, p1 = 0.f, p2 = 0.f, p3 = 0.f;
#pragma unroll
            for (int k = 0; k < 64; k += 4) {
                p0 += s_in[base + k] * s_w1[(base + k) * H_ + h];
                p1 += s_in[base + k + 1] * s_w1[(base + k + 1) * H_ + h];
                p2 += s_in[base + k + 2] * s_w1[(base + k + 2) * H_ + h];
                p3 += s_in[base + k + 3] * s_w1[(base + k + 3) * H_ + h];
            }
            s_pre[tid] = (p0 + p1) + (p2 + p3);
        }
        __syncthreads();
        if (tid < 256) s_h[tid] = fmaxf(r_mb1 + s_pre[tid] + s_pre[256 + tid], 0.f);
        __syncthreads();
        {
            int base = pq * 32;
            float q0 = 0.f, q1 = 0.f;
#pragma unroll
            for (int k = 0; k < 32; k += 2) {
                q0 += s_h[base + k] * s_w2[(base + k) * A_ + a];
                q1 += s_h[base + k + 1] * s_w2[(base + k + 1) * A_ + a];
            }
            s_part[tid] = q0 + q1;
        }
        __syncthreads();
        if (tid < 64) {
            float nm = r_mb2;
#pragma unroll
            for (int g = 0; g < 8; g++) nm += s_part[g * 64 + tid];
            float nv = (ops[b * L_ + t] == 0) ? nm : s_in[tid];
            s_in[tid] = nv;
            g_meta[(b * L_ + t) * A_ + tid] = nv;
        }
        __syncthreads();
    }
}

// ---------------- 3: proj (tinsum fused) --------------------------------------
__global__ void __launch_bounds__(256) k_proj(const float* __restrict__ cOut,
                                              const float* __restrict__ cIn) {
    int b = blockIdx.y;
    int tid = threadIdx.x;
    int w = tid >> 5, lane = tid & 31;
    __shared__ float s_arg[768];
    __shared__ float s_p[8][16];
    __shared__ float s_tin[64];
    if (tid < 64) s_tin[tid] = 0.f;
    for (int i = tid; i < 768; i += 256) s_arg[i] = g_arg[b * 768 + i];
    __syncthreads();
    int n = blockIdx.x * 8 + w;
    const float* rowO = (n < C_) ? cOut + (size_t)n * 64
                                 : g_objOut + (size_t)(b * O_ + n - C_) * 64;
    const float* rowI = (n < C_) ? cIn + (size_t)n * 64
                                 : g_objIn + (size_t)(b * O_ + n - C_) * 64;
    float x0 = rowO[lane], x1 = rowO[lane + 32];
    atomicAdd(&s_tin[lane], rowI[lane]);
    atomicAdd(&s_tin[lane + 32], rowI[lane + 32]);
#pragma unroll
    for (int s = 0; s < 12; s++) {
        float p = x0 * s_arg[s * 64 + lane] + x1 * s_arg[s * 64 + 32 + lane];
#pragma unroll
        for (int o = 16; o > 0; o >>= 1) p += __shfl_xor_sync(0xffffffffu, p, o);
        if (lane == 0) s_p[w][s] = p * (1.0f / 64.0f);
    }
    __syncwarp();
    if (lane < 16) {
        float v = (lane < 12) ? s_p[w][lane] : ((lane == 12) ? 1.0f : 0.0f);
        g_proj[(size_t)(b * N_ + n) * 16 + lane] = v;
        if (lane < 12) atomicAdd(&g_psum[b * 16 + lane], v);
    }
    __syncthreads();
    if (tid < 64) atomicAdd(&g_tInsum[b * 64 + tid], s_tin[tid]);
}

// ---------------- 4: big GEMM D_t = Hrel_t^T @ [tIn | proj | 1] ----------------
// 512 threads, tile 1h x 40c: h = tid&255, cg = tid>>8 (c base cg*40).
// Every 64-n tile is purely concept or object (C_ is 64-aligned) -> branch-free
// inner loop with linear T1 pointer.
__global__ void __launch_bounds__(512, 2) k_D(const int* __restrict__ ops,
                                              const float* __restrict__ cIn,
                                              const float* __restrict__ aw1,
                                              const float* __restrict__ ab1) {
    int t = blockIdx.y, b = blockIdx.z;
    if (ops[b * L_ + t] != 2) return;
    int tid = threadIdx.x;
    int h = tid & 255;
    int cg = tid >> 8;        // 0..1, c base = cg*40
    __shared__ float s_mt[64];
    __shared__ __align__(16) float s_u[256];
    __shared__ __align__(16) float s_X[64 * 80];
    if (tid < 64) s_mt[tid] = g_meta[(b * L_ + t) * A_ + tid];
    __syncthreads();
    if (tid < 256) {   // u[h] cooperative: thread tid computes h = tid
        float u0 = 0.f, u1 = 0.f, u2 = 0.f, u3 = 0.f;
#pragma unroll 4
        for (int a = 0; a < 64; a += 4) {
            u0 += s_mt[a] * __ldg(&aw1[(64 + a) * H_ + tid]);
            u1 += s_mt[a + 1] * __ldg(&aw1[(65 + a) * H_ + tid]);
            u2 += s_mt[a + 2] * __ldg(&aw1[(66 + a) * H_ + tid]);
            u3 += s_mt[a + 3] * __ldg(&aw1[(67 + a) * H_ + tid]);
        }
        s_u[tid] = ab1[tid] + ((u0 + u1) + (u2 + u3));
    }
    __syncthreads();
    float uh = s_u[h];

    unsigned long long acc[20];   // 40 c-values
#pragma unroll
    for (int j = 0; j < 20; j++) acc[j] = 0ULL;

    int nbase = blockIdx.x * 192;
    for (int tile = 0; tile < 3; tile++) {
        int n0 = nbase + tile * 64;
        bool isC = (n0 < C_);                       // whole tile on one side
        if (tile) __syncthreads();                  // previous X reads done
        {
            const float4* srcb = isC
                ? (const float4*)cIn + (size_t)n0 * 16
                : (const float4*)g_objIn + (size_t)(b * O_ + n0 - C_) * 16;
            float4* dst = (float4*)s_X;
            for (int i = tid; i < 1024; i += 512) {
                int r = i >> 4, c = i & 15;
                dst[r * 20 + c] = srcb[r * 16 + c];
            }
            if (tid < 256) {
                int r = tid >> 2, c = tid & 3;
                dst[r * 20 + 16 + c] =
                    ((const float4*)g_proj)[(size_t)(b * N_ + n0 + r) * 4 + c];
            }
        }
        __syncthreads();
        const float* t1p = (isC ? g_T1c + (size_t)n0 * H_
                                : g_T1o + (size_t)(b * O_ + n0 - C_) * H_) + h;
        // depth-2 prefetch, linear pointer
        float t1a = t1p[0];
        float t1b = t1p[H_];
        t1p += 2 * H_;
        for (int nl = 0; nl < 64; nl++) {
            float hv = fmaxf(t1a + uh, 0.f);
            t1a = t1b;
            if (nl < 62) { t1b = *t1p; t1p += H_; }
            unsigned long long hv2 = pack2(hv);
            const ulonglong2* xr = (const ulonglong2*)(s_X + nl * 80 + cg * 40);
#pragma unroll
            for (int j = 0; j < 10; j++) {
                ulonglong2 p = xr[j];
                asm("fma.rn.f32x2 %0, %1, %2, %0;" : "+l"(acc[2 * j]) : "l"(hv2), "l"(p.x));
                asm("fma.rn.f32x2 %0, %1, %2, %0;" : "+l"(acc[2 * j + 1]) : "l"(hv2), "l"(p.y));
            }
        }
    }
    float* dp = g_D + ((size_t)(b * L_ + t) * H_ + h) * DCOLS + cg * 40;
#pragma unroll
    for (int j = 0; j < 20; j++) {
        asm volatile("red.global.add.v2.f32 [%0], {%1, %2};"
                     :: "l"(dp + 2 * j), "f"(lo2(acc[j])), "f"(hi2(acc[j])) : "memory");
    }
}

// ---------------- 5: k_E: E_t = W2^T @ D_t  (stored transposed [c][e']) --------
__global__ void __launch_bounds__(256) k_E(const int* __restrict__ ops,
                                           const float* __restrict__ w2) {
    int t = blockIdx.x, b = blockIdx.y;
    if (ops[b * L_ + t] != 2) return;
    int tid = threadIdx.x;
    int ep = tid & 63;
    int cq = tid >> 6;
    __shared__ __align__(16) float s_D[64 * 80];
    __shared__ __align__(16) float s_w2[64 * 64];
    unsigned long long acc[10];
#pragma unroll
    for (int j = 0; j < 10; j++) acc[j] = 0ULL;
    size_t dbase = (size_t)(b * L_ + t) * H_ * DCOLS;
    for (int ch = 0; ch < 4; ch++) {
        __syncthreads();
        {
            const float4* src = (const float4*)(g_D + dbase + ch * 64 * DCOLS);
            float4* dst = (float4*)s_D;
            for (int i = tid; i < 1280; i += 256) dst[i] = src[i];
            const float4* wsrc = (const float4*)(w2 + ch * 64 * 64);
            float4* wdst = (float4*)s_w2;
            for (int i = tid; i < 1024; i += 256) wdst[i] = wsrc[i];
        }
        __syncthreads();
        const unsigned long long* D2 = (const unsigned long long*)s_D;
#pragma unroll 8
        for (int hh = 0; hh < 64; hh++) {
            unsigned long long w2v = pack2(s_w2[hh * 64 + ep]);
            const unsigned long long* drow = D2 + hh * 40 + cq * 10;
#pragma unroll
            for (int j = 0; j < 10; j++) {
                asm("fma.rn.f32x2 %0, %1, %2, %0;" : "+l"(acc[j]) : "l"(w2v), "l"(drow[j]));
            }
        }
    }
    float* eb = g_E + (size_t)(b * L_ + t) * DCOLS * 64;
#pragma unroll
    for (int j = 0; j < 10; j++) {
        int c = cq * 20 + 2 * j;
        eb[c * 64 + ep] = lo2(acc[j]);
        eb[(c + 1) * 64 + ep] = hi2(acc[j]);
    }
}

// ---------------- 6: tiny serial recurrence: Msum, attsum ----------------------
__global__ void __launch_bounds__(1024) k_rec(const int* __restrict__ ops,
                                              const float* __restrict__ b2,
                                              const float* __restrict__ att_init) {
    __shared__ __align__(16) float s_Ms[4096];
    __shared__ __align__(16) float s_E[5120];
    __shared__ float s_meta[768], s_tmp[1024];
    __shared__ float s_as[64], s_ai[64], s_tis[64], s_b2[64], s_ps[12];
    __shared__ int s_op[12];
    int b = blockIdx.x, tid = threadIdx.x;
    for (int i = tid; i < 4096; i += 1024) s_Ms[i] = 0.f;
    if (tid < 768) s_meta[tid] = g_meta[b * 768 + tid];
    if (tid < 64) {
        s_ai[tid] = att_init[tid];
        s_as[tid] = (float)N_ * att_init[tid];
        s_tis[tid] = g_tInsum[b * 64 + tid];
        s_b2[tid] = b2[tid];
    }
    if (tid < 12) { s_op[tid] = ops[b * L_ + tid]; s_ps[tid] = g_psum[b * 16 + tid]; }
    __syncthreads();
    const float invN = 1.0f / (float)N_;
    int a = tid & 63, eg = tid >> 6;
    int e0 = eg * 4;
    for (int t = 0; t < L_; t++) {
        int op = s_op[t];
        if (op == 1) {
            if (tid < 64) s_as[tid] += s_ps[t] * s_meta[t * 64 + tid];
            __syncthreads();
        } else if (op == 2) {
            const float* esrc = g_E + (size_t)(b * L_ + t) * 5120;
            for (int i = tid; i < 5120; i += 1024) s_E[i] = esrc[i];
            __syncthreads();
            unsigned long long ai2 = pack2(s_ai[a]);
            unsigned long long acc2[2], bcc2[2];
            {
                ulonglong2 es = *(const ulonglong2*)(s_E + 76 * 64 + e0);
                acc2[0] = 0ULL; acc2[1] = 0ULL; bcc2[0] = 0ULL; bcc2[1] = 0ULL;
                asm("fma.rn.f32x2 %0, %1, %2, %0;" : "+l"(acc2[0]) : "l"(es.x), "l"(ai2));
                asm("fma.rn.f32x2 %0, %1, %2, %0;" : "+l"(acc2[1]) : "l"(es.y), "l"(ai2));
            }
            for (int s = 0; s < t; s++)
                if (s_op[s] == 1) {
                    unsigned long long mv = pack2(s_meta[s * 64 + a]);
                    ulonglong2 er = *(const ulonglong2*)(s_E + (64 + s) * 64 + e0);
                    asm("fma.rn.f32x2 %0, %1, %2, %0;" : "+l"(acc2[0]) : "l"(er.x), "l"(mv));
                    asm("fma.rn.f32x2 %0, %1, %2, %0;" : "+l"(acc2[1]) : "l"(er.y), "l"(mv));
                }
#pragma unroll 4
            for (int e = 0; e < 64; e += 2) {
                unsigned long long m0 = pack2(s_Ms[e * 64 + a]);
                ulonglong2 k0 = *(const ulonglong2*)(s_E + e * 64 + e0);
                asm("fma.rn.f32x2 %0, %1, %2, %0;" : "+l"(acc2[0]) : "l"(k0.x), "l"(m0));
                asm("fma.rn.f32x2 %0, %1, %2, %0;" : "+l"(acc2[1]) : "l"(k0.y), "l"(m0));
                unsigned long long m1 = pack2(s_Ms[(e + 1) * 64 + a]);
                ulonglong2 k1 = *(const ulonglong2*)(s_E + (e + 1) * 64 + e0);
                asm("fma.rn.f32x2 %0, %1, %2, %0;" : "+l"(bcc2[0]) : "l"(k1.x), "l"(m1));
                asm("fma.rn.f32x2 %0, %1, %2, %0;" : "+l"(bcc2[1]) : "l"(k1.y), "l"(m1));
            }
            float asv = s_as[a];
            float m[4] = {lo2(acc2[0]) + lo2(bcc2[0]), hi2(acc2[0]) + hi2(bcc2[0]),
                          lo2(acc2[1]) + lo2(bcc2[1]), hi2(acc2[1]) + hi2(bcc2[1])};
            float part = 0.f;
#pragma unroll
            for (int j = 0; j < 4; j++) {
                m[j] = (m[j] + s_b2[e0 + j] * asv) * invN;
                part += s_tis[e0 + j] * m[j];
            }
            s_tmp[eg * 64 + a] = part;
            __syncthreads();
#pragma unroll
            for (int j = 0; j < 4; j++) s_Ms[(e0 + j) * 64 + a] += m[j];
            if (tid < 64) {
                float d = 0.f;
#pragma unroll
                for (int g = 0; g < 16; g++) d += s_tmp[g * 64 + tid];
                s_as[tid] += d;
            }
            __syncthreads();
        }
    }
    for (int i = tid; i < 4096; i += 1024) g_Msum[b * 4096 + i] = s_Ms[i];
}

// ---------------- 7: final: att rows, ol, max (32 rows/block) ------------------
__global__ void __launch_bounds__(128) k_final(const int* __restrict__ ops,
                                               const float* __restrict__ cIn,
                                               const float* __restrict__ att_init) {
    int b = blockIdx.y;
    int ag = threadIdx.x;
    int ny = threadIdx.y;
    int tid = ny * 16 + ag;
    __shared__ float s_Ms[4096], s_meta[768], s_ai[64];
    __shared__ float s_ti[8][64], s_pr[8][16];
    __shared__ int s_opf[12];
    for (int i = tid; i < 4096; i += 128) s_Ms[i] = g_Msum[b * 4096 + i];
    for (int i = tid; i < 768; i += 128) s_meta[i] = g_meta[b * 768 + i];
    if (tid < 64) s_ai[tid] = att_init[tid];
    if (tid < 12) s_opf[tid] = ops[b * L_ + tid];
    int base = blockIdx.x * 32;
    for (int g4 = 0; g4 < 4; g4++) {
        int n0 = base + g4 * 8;
        __syncthreads();
        for (int i = tid; i < 512; i += 128) {
            int r = i >> 6, e = i & 63;
            int n = n0 + r;
            const float* row = (n < C_) ? cIn + (size_t)n * 64
                                        : g_objIn + (size_t)(b * O_ + n - C_) * 64;
            s_ti[r][e] = row[e];
        }
        {
            int r = tid >> 4, c = tid & 15;
            s_pr[r][c] = g_proj[(size_t)(b * N_ + n0 + r) * 16 + c];
        }
        __syncthreads();
        int n = n0 + ny;
        int a0 = ag * 4;
        float v0 = s_ai[a0], v1 = s_ai[a0 + 1], v2 = s_ai[a0 + 2], v3 = s_ai[a0 + 3];
#pragma unroll
        for (int s = 0; s < 12; s++)
            if (s_opf[s] == 1) {
                float pp = s_pr[ny][s];
                v0 += pp * s_meta[s * 64 + a0];
                v1 += pp * s_meta[s * 64 + a0 + 1];
                v2 += pp * s_meta[s * 64 + a0 + 2];
                v3 += pp * s_meta[s * 64 + a0 + 3];
            }
        const float4* Ms4 = (const float4*)s_Ms;
#pragma unroll
        for (int e = 0; e < 64; e++) {
            float ti = s_ti[ny][e];
            float4 m = Ms4[e * 16 + ag];
            v0 += ti * m.x; v1 += ti * m.y; v2 += ti * m.z; v3 += ti * m.w;
        }
        float sq = v0 * v0 + v1 * v1 + v2 * v2 + v3 * v3;
#pragma unroll
        for (int o = 8; o > 0; o >>= 1) sq += __shfl_xor_sync(0xffffffffu, sq, o);
        if (ag == 0) {
            float ol = sq * (1.0f / 64.0f);
            g_ol[b * N_ + n] = ol;
            atomicMax(&g_olmax[b], __float_as_int(ol));  // ol >= 0
        }
    }
}

// ---------------- 8: softmax ----------------------------------------------------
__global__ void __launch_bounds__(1024) k_soft(float* __restrict__ out) {
    int b = blockIdx.x;
    int tid = threadIdx.x;
    __shared__ float s_red[1024];
    float mx = __int_as_float(g_olmax[b]);
    float lsum = 0.f;
    for (int n = tid; n < N_; n += 1024) lsum += expf(g_ol[b * N_ + n] - mx);
    s_red[tid] = lsum;
    __syncthreads();
    for (int s = 512; s > 0; s >>= 1) {
        if (tid < s) s_red[tid] += s_red[tid + s];
        __syncthreads();
    }
    float lse = logf(s_red[0]) + mx;
    for (int n = tid; n < N_; n += 1024) out[b * N_ + n] = g_ol[b * N_ + n] - lse;
}

// ---------------- launch --------------------------------------------------------
extern "C" void kernel_launch(void* const* d_in, const int* in_sizes, int n_in,
                              void* d_out, int out_size) {
    const float* class_embIn   = (const float*)d_in[0];
    const float* class_embOut  = (const float*)d_in[1];
    const float* attr_embIn    = (const float*)d_in[2];
    const float* attr_embOut   = (const float*)d_in[3];
    const float* concept_embIn = (const float*)d_in[4];
    const float* concept_embOut= (const float*)d_in[5];
    const float* meta_init     = (const float*)d_in[6];
    const float* attention_init= (const float*)d_in[8];
    const float* axon_w1       = (const float*)d_in[9];
    const float* axon_b1       = (const float*)d_in[10];
    const float* axon_w2       = (const float*)d_in[11];
    const float* axon_b2       = (const float*)d_in[12];
    const float* meta_w1       = (const float*)d_in[13];
    const float* meta_b1       = (const float*)d_in[14];
    const float* meta_w2       = (const float*)d_in[15];
    const float* meta_b2       = (const float*)d_in[16];
    const int*   program_ops   = (const int*)d_in[17];
    const int*   program_args  = (const int*)d_in[18];
    const int*   gt_classes    = (const int*)d_in[19];
    const int*   gt_attributes = (const int*)d_in[20];
    float* out = (float*)d_out;

    cudaFuncSetAttribute(k_meta, cudaFuncAttributeMaxDynamicSharedMemorySize,
                         49152 * (int)sizeof(float));  // 192 KB

    k_pre<<<345, 256>>>(class_embIn, class_embOut, attr_embIn, attr_embOut,   // 1
                        gt_classes, gt_attributes, axon_w1, concept_embOut,
                        program_args);
    k_meta<<<B_, 512, 49152 * sizeof(float)>>>(meta_init, meta_w1, meta_b1,   // 2
                                               meta_w2, meta_b2, program_ops);
    k_proj<<<dim3(N_ / 8, B_), 256>>>(concept_embOut, concept_embIn);         // 3
    k_D<<<dim3(N_ / 192, L_, B_), 512>>>(program_ops, concept_embIn,          // 4
                                         axon_w1, axon_b1);
    k_E<<<dim3(L_, B_), 256>>>(program_ops, axon_w2);                         // 5
    k_rec<<<B_, 1024>>>(program_ops, axon_b2, attention_init);                // 6
    k_final<<<dim3(N_ / 32, B_), dim3(16, 8)>>>(program_ops, concept_embIn,   // 7
                                                attention_init);
    k_soft<<<B_, 1024>>>(out);                                                // 8
}

// round 12
// speedup vs baseline: 1.2141x; 1.2141x over previous
#include <cuda_runtime.h>

// Problem constants
constexpr int B_ = 8, L_ = 12, C_ = 4096, O_ = 128, N_ = 4224;
constexpr int E_ = 64, A_ = 64, H_ = 256;
constexpr int DCOLS = 80;  // X cols: 0..63 tIn, 64..75 proj_s, 76 = ones, 77..79 pad

// ---------------- scratch (device globals) ----------------------------------
__device__ __align__(16) float g_objIn[B_ * O_ * E_];
__device__ __align__(16) float g_objOut[B_ * O_ * E_];
__device__ __align__(16) float g_T1c[C_ * H_];
__device__ __align__(16) float g_T1o[B_ * O_ * H_];
__device__ __align__(16) float g_meta[B_ * L_ * A_];
__device__ __align__(16) float g_arg[B_ * L_ * E_];
__device__ __align__(16) float g_proj[B_ * N_ * 16];
__device__ __align__(16) float g_psum[B_ * 16];
__device__ __align__(16) float g_tInsum[B_ * E_];
__device__ __align__(16) float g_D[B_ * L_ * H_ * DCOLS];   // [bt][h][c]
__device__ __align__(16) float g_E[B_ * L_ * DCOLS * 64];   // [bt][c][e'] (transposed)
__device__ __align__(16) float g_Msum[B_ * E_ * A_];
__device__ __align__(16) float g_ol[B_ * N_];
__device__ int g_olmax[B_];

__device__ __forceinline__ unsigned long long pack2(float v) {
    unsigned int b = __float_as_uint(v);
    return ((unsigned long long)b << 32) | b;
}
__device__ __forceinline__ float lo2(unsigned long long v) {
    return __uint_as_float((unsigned)(v & 0xffffffffULL));
}
__device__ __forceinline__ float hi2(unsigned long long v) {
    return __uint_as_float((unsigned)(v >> 32));
}

// ---------------- 1: fused precompute: T1c | objT1o | zero | arg gather -------
// blocks: [0,256) T1c, [256,320) objT1o, [320,344) zero, [344] arg gather
__global__ void __launch_bounds__(256) k_pre(
    const float* __restrict__ clsIn, const float* __restrict__ clsOut,
    const float* __restrict__ atIn, const float* __restrict__ atOut,
    const int* __restrict__ gt_cls, const int* __restrict__ gt_attr,
    const float* __restrict__ w1, const float* __restrict__ cOut,
    const int* __restrict__ args) {
    int bx = blockIdx.x;
    int tid = threadIdx.x;
    __shared__ float s_emb[1024];
    __shared__ float s_w[4096];

    if (bx < 256) {
        int n0 = bx * 16;
        for (int i = tid; i < 1024; i += 256) s_emb[i] = cOut[n0 * E_ + i];
        float acc[16];
#pragma unroll
        for (int r = 0; r < 16; r++) acc[r] = 0.f;
        for (int ch = 0; ch < 4; ch++) {
            __syncthreads();
            {
                const float4* src = (const float4*)(w1 + ch * 16 * H_);
                float4* dst = (float4*)s_w;
                for (int i = tid; i < 1024; i += 256) dst[i] = src[i];
            }
            __syncthreads();
#pragma unroll
            for (int e = 0; e < 16; e++) {
                float w = s_w[e * H_ + tid];
                int ge = ch * 16 + e;
#pragma unroll
                for (int r = 0; r < 16; r++) acc[r] += s_emb[r * 64 + ge] * w;
            }
        }
#pragma unroll
        for (int r = 0; r < 16; r++) g_T1c[(n0 + r) * H_ + tid] = acc[r];
    } else if (bx < 320) {
        int idx = bx - 256;
        int b = idx >> 3;
        int o0 = (idx & 7) * 16;
        for (int i = tid; i < 1024; i += 256) {
            int r = i >> 6, e = i & 63;
            int o = o0 + r;
            int cls = gt_cls[b * O_ + o];
            float vi = clsIn[cls * E_ + e];
            float vo = clsOut[cls * E_ + e];
#pragma unroll
            for (int k = 0; k < 8; k++) {
                int at = gt_attr[(b * O_ + o) * 8 + k];
                vi += atIn[at * E_ + e];
                vo += atOut[at * E_ + e];
            }
            g_objIn[(b * O_ + o) * E_ + e] = vi;
            g_objOut[(b * O_ + o) * E_ + e] = vo;
            s_emb[i] = vo;
        }
        float acc[16];
#pragma unroll
        for (int r = 0; r < 16; r++) acc[r] = 0.f;
        for (int ch = 0; ch < 4; ch++) {
            __syncthreads();
            {
                const float4* src = (const float4*)(w1 + ch * 16 * H_);
                float4* dst = (float4*)s_w;
                for (int i = tid; i < 1024; i += 256) dst[i] = src[i];
            }
            __syncthreads();
#pragma unroll
            for (int e = 0; e < 16; e++) {
                float w = s_w[e * H_ + tid];
                int ge = ch * 16 + e;
#pragma unroll
                for (int r = 0; r < 16; r++) acc[r] += s_emb[r * 64 + ge] * w;
            }
        }
#pragma unroll
        for (int r = 0; r < 16; r++) g_T1o[(b * O_ + o0 + r) * H_ + tid] = acc[r];
    } else if (bx < 344) {
        int i = (bx - 320) * 256 + tid;   // 0..6143
        float4 z = make_float4(0.f, 0.f, 0.f, 0.f);
        float4* d4 = (float4*)g_D;
#pragma unroll
        for (int j = 0; j < 80; j++) d4[j * 6144 + i] = z;
        if (bx == 320) {
            if (tid < 128) g_psum[tid] = 0.f;
            g_tInsum[tid] = 0.f;
            g_tInsum[256 + tid] = 0.f;
            if (tid < 8) g_olmax[tid] = 0;
        }
    } else {
        for (int i = tid; i < B_ * L_ * E_; i += 256) {
            int bt = i >> 6, e = i & 63;
            g_arg[i] = cOut[args[bt] * E_ + e];
        }
    }
}

// ---------------- 2: meta recurrence (512 threads, split-K) -------------------
__global__ void __launch_bounds__(512) k_meta(
    const float* __restrict__ meta_init,
    const float* __restrict__ mw1, const float* __restrict__ mb1,
    const float* __restrict__ mw2, const float* __restrict__ mb2,
    const int* __restrict__ ops) {
    extern __shared__ float dsm[];
    float* s_w1 = dsm;             // 128*256 (full meta_w1)
    float* s_w2 = dsm + 32768;     // 256*64
    __shared__ float s_in[128];    // [meta(64) | arg(64)]
    __shared__ float s_h[256], s_pre[512], s_part[512];
    int b = blockIdx.x;
    int tid = threadIdx.x;
    {
        const float4* w1_4 = (const float4*)mw1;
        float4* d1 = (float4*)s_w1;
        for (int i = tid; i < 8192; i += 512) d1[i] = w1_4[i];
        const float4* w2_4 = (const float4*)mw2;
        float4* d2 = (float4*)s_w2;
        for (int i = tid; i < 4096; i += 512) d2[i] = w2_4[i];
    }
    float r_mb1 = (tid < 256) ? mb1[tid] : 0.f;
    float r_mb2 = (tid < 64) ? mb2[tid] : 0.f;
    if (tid < 64) s_in[tid] = meta_init[tid];
    __syncthreads();
    int h = tid & 255, half = tid >> 8;
    int a = tid & 63, pq = tid >> 6;
    for (int t = 0; t < L_; t++) {
        if (tid < 64) s_in[64 + tid] = g_arg[(b * L_ + t) * E_ + tid];
        __syncthreads();
        {
            int base = half * 64;
            float p0 = 0.f, p1 = 0.f, p2 = 0.f, p3 = 0.f;
#pragma unroll
            for (int k = 0; k < 64; k += 4) {
                p0 += s_in[base + k] * s_w1[(base + k) * H_ + h];
                p1 += s_in[base + k + 1] * s_w1[(base + k + 1) * H_ + h];
                p2 += s_in[base + k + 2] * s_w1[(base + k + 2) * H_ + h];
                p3 += s_in[base + k + 3] * s_w1[(base + k + 3) * H_ + h];
            }
            s_pre[tid] = (p0 + p1) + (p2 + p3);
        }
        __syncthreads();
        if (tid < 256) s_h[tid] = fmaxf(r_mb1 + s_pre[tid] + s_pre[256 + tid], 0.f);
        __syncthreads();
        {
            int base = pq * 32;
            float q0 = 0.f, q1 = 0.f;
#pragma unroll
            for (int k = 0; k < 32; k += 2) {
                q0 += s_h[base + k] * s_w2[(base + k) * A_ + a];
                q1 += s_h[base + k + 1] * s_w2[(base + k + 1) * A_ + a];
            }
            s_part[tid] = q0 + q1;
        }
        __syncthreads();
        if (tid < 64) {
            float nm = r_mb2;
#pragma unroll
            for (int g = 0; g < 8; g++) nm += s_part[g * 64 + tid];
            float nv = (ops[b * L_ + t] == 0) ? nm : s_in[tid];
            s_in[tid] = nv;
            g_meta[(b * L_ + t) * A_ + tid] = nv;
        }
        __syncthreads();
    }
}

// ---------------- 3: proj (tinsum fused) --------------------------------------
__global__ void __launch_bounds__(256) k_proj(const float* __restrict__ cOut,
                                              const float* __restrict__ cIn) {
    int b = blockIdx.y;
    int tid = threadIdx.x;
    int w = tid >> 5, lane = tid & 31;
    __shared__ float s_arg[768];
    __shared__ float s_p[8][16];
    __shared__ float s_tin[64];
    if (tid < 64) s_tin[tid] = 0.f;
    for (int i = tid; i < 768; i += 256) s_arg[i] = g_arg[b * 768 + i];
    __syncthreads();
    int n = blockIdx.x * 8 + w;
    const float* rowO = (n < C_) ? cOut + (size_t)n * 64
                                 : g_objOut + (size_t)(b * O_ + n - C_) * 64;
    const float* rowI = (n < C_) ? cIn + (size_t)n * 64
                                 : g_objIn + (size_t)(b * O_ + n - C_) * 64;
    float x0 = rowO[lane], x1 = rowO[lane + 32];
    atomicAdd(&s_tin[lane], rowI[lane]);
    atomicAdd(&s_tin[lane + 32], rowI[lane + 32]);
#pragma unroll
    for (int s = 0; s < 12; s++) {
        float p = x0 * s_arg[s * 64 + lane] + x1 * s_arg[s * 64 + 32 + lane];
#pragma unroll
        for (int o = 16; o > 0; o >>= 1) p += __shfl_xor_sync(0xffffffffu, p, o);
        if (lane == 0) s_p[w][s] = p * (1.0f / 64.0f);
    }
    __syncwarp();
    if (lane < 16) {
        float v = (lane < 12) ? s_p[w][lane] : ((lane == 12) ? 1.0f : 0.0f);
        g_proj[(size_t)(b * N_ + n) * 16 + lane] = v;
        if (lane < 12) atomicAdd(&g_psum[b * 16 + lane], v);
    }
    __syncthreads();
    if (tid < 64) atomicAdd(&g_tInsum[b * 64 + tid], s_tin[tid]);
}

// ---------------- 4: big GEMM D_t = Hrel_t^T @ [tIn | proj | 1] ----------------
// 256 threads, tile 4h x 20c (hg = tid&63 -> h=hg*4, cg = tid>>6 -> c=cg*20).
// One 64-n tile per block (fine-grained waves); t1 prefetch depth 4.
__global__ void __launch_bounds__(256, 2) k_D(const int* __restrict__ ops,
                                              const float* __restrict__ cIn,
                                              const float* __restrict__ aw1,
                                              const float* __restrict__ ab1) {
    int t = blockIdx.y, b = blockIdx.z;
    if (ops[b * L_ + t] != 2) return;
    int tid = threadIdx.x;
    int hg = tid & 63;        // h base = hg*4
    int cg = tid >> 6;        // c base = cg*20
    __shared__ float s_mt[64];
    __shared__ __align__(16) float s_u[256];
    __shared__ __align__(16) float s_X[64 * 80];
    if (tid < 64) s_mt[tid] = g_meta[(b * L_ + t) * A_ + tid];
    __syncthreads();
    {   // u[h] cooperative: thread tid computes h = tid
        float u0 = 0.f, u1 = 0.f, u2 = 0.f, u3 = 0.f;
#pragma unroll 4
        for (int a = 0; a < 64; a += 4) {
            u0 += s_mt[a] * __ldg(&aw1[(64 + a) * H_ + tid]);
            u1 += s_mt[a + 1] * __ldg(&aw1[(65 + a) * H_ + tid]);
            u2 += s_mt[a + 2] * __ldg(&aw1[(66 + a) * H_ + tid]);
            u3 += s_mt[a + 3] * __ldg(&aw1[(67 + a) * H_ + tid]);
        }
        s_u[tid] = ab1[tid] + ((u0 + u1) + (u2 + u3));
    }
    __syncthreads();
    float4 uv = *(const float4*)(s_u + hg * 4);

    unsigned long long acc[40];   // [i=h-sub][j=0..9] -> acc[i*10+j]
#pragma unroll
    for (int j = 0; j < 40; j++) acc[j] = 0ULL;

    int n0 = blockIdx.x * 64;
    bool isC = (n0 < C_);   // whole 64-tile is one side (C_ 64-aligned)
    {   // stage X tile
        const float4* srcb = isC
            ? (const float4*)cIn + (size_t)n0 * 16
            : (const float4*)g_objIn + (size_t)(b * O_ + n0 - C_) * 16;
        float4* dst = (float4*)s_X;
        for (int i = tid; i < 1024; i += 256) {
            int r = i >> 4, c = i & 15;
            dst[r * 20 + c] = srcb[r * 16 + c];
        }
        {
            int r = tid >> 2, c = tid & 3;
            dst[r * 20 + 16 + c] =
                ((const float4*)g_proj)[(size_t)(b * N_ + n0 + r) * 4 + c];
        }
    }
    __syncthreads();

    // T1 float4 pointer for this thread's 4 h-values; stride 64 float4 per n.
    const float4* t1p = (const float4*)(isC ? g_T1c + (size_t)n0 * H_
                                            : g_T1o + (size_t)(b * O_ + n0 - C_) * H_) + hg;
    // depth-4 prefetch ring
    float4 r0 = t1p[0], r1 = t1p[64], r2 = t1p[128], r3 = t1p[192];
    t1p += 256;

#define KD_STEP(CUR, LOADOK)                                                     \
    do {                                                                         \
        float4 cur = (CUR);                                                      \
        if (LOADOK) { (CUR) = *t1p; t1p += 64; }                                 \
        unsigned long long hv2_0 = pack2(fmaxf(cur.x + uv.x, 0.f));              \
        unsigned long long hv2_1 = pack2(fmaxf(cur.y + uv.y, 0.f));              \
        unsigned long long hv2_2 = pack2(fmaxf(cur.z + uv.z, 0.f));              \
        unsigned long long hv2_3 = pack2(fmaxf(cur.w + uv.w, 0.f));              \
        const ulonglong2* xr = (const ulonglong2*)(s_X + nl_base * 80 + cg * 20);\
        _Pragma("unroll")                                                        \
        for (int j = 0; j < 5; j++) {                                            \
            ulonglong2 p = xr[j];                                                \
            asm("fma.rn.f32x2 %0, %1, %2, %0;" : "+l"(acc[0 * 10 + 2 * j]) : "l"(hv2_0), "l"(p.x)); \
            asm("fma.rn.f32x2 %0, %1, %2, %0;" : "+l"(acc[0 * 10 + 2 * j + 1]) : "l"(hv2_0), "l"(p.y)); \
            asm("fma.rn.f32x2 %0, %1, %2, %0;" : "+l"(acc[1 * 10 + 2 * j]) : "l"(hv2_1), "l"(p.x)); \
            asm("fma.rn.f32x2 %0, %1, %2, %0;" : "+l"(acc[1 * 10 + 2 * j + 1]) : "l"(hv2_1), "l"(p.y)); \
            asm("fma.rn.f32x2 %0, %1, %2, %0;" : "+l"(acc[2 * 10 + 2 * j]) : "l"(hv2_2), "l"(p.x)); \
            asm("fma.rn.f32x2 %0, %1, %2, %0;" : "+l"(acc[2 * 10 + 2 * j + 1]) : "l"(hv2_2), "l"(p.y)); \
            asm("fma.rn.f32x2 %0, %1, %2, %0;" : "+l"(acc[3 * 10 + 2 * j]) : "l"(hv2_3), "l"(p.x)); \
            asm("fma.rn.f32x2 %0, %1, %2, %0;" : "+l"(acc[3 * 10 + 2 * j + 1]) : "l"(hv2_3), "l"(p.y)); \
        }                                                                        \
        nl_base++;                                                               \
    } while (0)

    int nl_base = 0;
    for (int nb = 0; nb < 16; nb++) {
        bool ok = (nb < 15);
        KD_STEP(r0, ok);
        KD_STEP(r1, ok);
        KD_STEP(r2, ok);
        KD_STEP(r3, ok);
    }
#undef KD_STEP

#pragma unroll
    for (int i = 0; i < 4; i++) {
        float* dp = g_D + ((size_t)(b * L_ + t) * H_ + hg * 4 + i) * DCOLS + cg * 20;
#pragma unroll
        for (int j = 0; j < 10; j++) {
            asm volatile("red.global.add.v2.f32 [%0], {%1, %2};"
                         :: "l"(dp + 2 * j), "f"(lo2(acc[i * 10 + j])),
                            "f"(hi2(acc[i * 10 + j])) : "memory");
        }
    }
}

// ---------------- 5: k_E: E_t = W2^T @ D_t  (stored transposed [c][e']) --------
__global__ void __launch_bounds__(256) k_E(const int* __restrict__ ops,
                                           const float* __restrict__ w2) {
    int t = blockIdx.x, b = blockIdx.y;
    if (ops[b * L_ + t] != 2) return;
    int tid = threadIdx.x;
    int ep = tid & 63;
    int cq = tid >> 6;
    __shared__ __align__(16) float s_D[64 * 80];
    __shared__ __align__(16) float s_w2[64 * 64];
    unsigned long long acc[10];
#pragma unroll
    for (int j = 0; j < 10; j++) acc[j] = 0ULL;
    size_t dbase = (size_t)(b * L_ + t) * H_ * DCOLS;
    for (int ch = 0; ch < 4; ch++) {
        __syncthreads();
        {
            const float4* src = (const float4*)(g_D + dbase + ch * 64 * DCOLS);
            float4* dst = (float4*)s_D;
            for (int i = tid; i < 1280; i += 256) dst[i] = src[i];
            const float4* wsrc = (const float4*)(w2 + ch * 64 * 64);
            float4* wdst = (float4*)s_w2;
            for (int i = tid; i < 1024; i += 256) wdst[i] = wsrc[i];
        }
        __syncthreads();
        const unsigned long long* D2 = (const unsigned long long*)s_D;
#pragma unroll 8
        for (int hh = 0; hh < 64; hh++) {
            unsigned long long w2v = pack2(s_w2[hh * 64 + ep]);
            const unsigned long long* drow = D2 + hh * 40 + cq * 10;
#pragma unroll
            for (int j = 0; j < 10; j++) {
                asm("fma.rn.f32x2 %0, %1, %2, %0;" : "+l"(acc[j]) : "l"(w2v), "l"(drow[j]));
            }
        }
    }
    float* eb = g_E + (size_t)(b * L_ + t) * DCOLS * 64;
#pragma unroll
    for (int j = 0; j < 10; j++) {
        int c = cq * 20 + 2 * j;
        eb[c * 64 + ep] = lo2(acc[j]);
        eb[(c + 1) * 64 + ep] = hi2(acc[j]);
    }
}

// ---------------- 6: tiny serial recurrence: Msum, attsum ----------------------
__global__ void __launch_bounds__(1024) k_rec(const int* __restrict__ ops,
                                              const float* __restrict__ b2,
                                              const float* __restrict__ att_init) {
    __shared__ __align__(16) float s_Ms[4096];
    __shared__ __align__(16) float s_E[5120];
    __shared__ float s_meta[768], s_tmp[1024];
    __shared__ float s_as[64], s_ai[64], s_tis[64], s_b2[64], s_ps[12];
    __shared__ int s_op[12];
    int b = blockIdx.x, tid = threadIdx.x;
    for (int i = tid; i < 4096; i += 1024) s_Ms[i] = 0.f;
    if (tid < 768) s_meta[tid] = g_meta[b * 768 + tid];
    if (tid < 64) {
        s_ai[tid] = att_init[tid];
        s_as[tid] = (float)N_ * att_init[tid];
        s_tis[tid] = g_tInsum[b * 64 + tid];
        s_b2[tid] = b2[tid];
    }
    if (tid < 12) { s_op[tid] = ops[b * L_ + tid]; s_ps[tid] = g_psum[b * 16 + tid]; }
    __syncthreads();
    const float invN = 1.0f / (float)N_;
    int a = tid & 63, eg = tid >> 6;
    int e0 = eg * 4;
    for (int t = 0; t < L_; t++) {
        int op = s_op[t];
        if (op == 1) {
            if (tid < 64) s_as[tid] += s_ps[t] * s_meta[t * 64 + tid];
            __syncthreads();
        } else if (op == 2) {
            const float* esrc = g_E + (size_t)(b * L_ + t) * 5120;
            for (int i = tid; i < 5120; i += 1024) s_E[i] = esrc[i];
            __syncthreads();
            unsigned long long ai2 = pack2(s_ai[a]);
            unsigned long long acc2[2], bcc2[2];
            {
                ulonglong2 es = *(const ulonglong2*)(s_E + 76 * 64 + e0);
                acc2[0] = 0ULL; acc2[1] = 0ULL; bcc2[0] = 0ULL; bcc2[1] = 0ULL;
                asm("fma.rn.f32x2 %0, %1, %2, %0;" : "+l"(acc2[0]) : "l"(es.x), "l"(ai2));
                asm("fma.rn.f32x2 %0, %1, %2, %0;" : "+l"(acc2[1]) : "l"(es.y), "l"(ai2));
            }
            for (int s = 0; s < t; s++)
                if (s_op[s] == 1) {
                    unsigned long long mv = pack2(s_meta[s * 64 + a]);
                    ulonglong2 er = *(const ulonglong2*)(s_E + (64 + s) * 64 + e0);
                    asm("fma.rn.f32x2 %0, %1, %2, %0;" : "+l"(acc2[0]) : "l"(er.x), "l"(mv));
                    asm("fma.rn.f32x2 %0, %1, %2, %0;" : "+l"(acc2[1]) : "l"(er.y), "l"(mv));
                }
#pragma unroll 4
            for (int e = 0; e < 64; e += 2) {
                unsigned long long m0 = pack2(s_Ms[e * 64 + a]);
                ulonglong2 k0 = *(const ulonglong2*)(s_E + e * 64 + e0);
                asm("fma.rn.f32x2 %0, %1, %2, %0;" : "+l"(acc2[0]) : "l"(k0.x), "l"(m0));
                asm("fma.rn.f32x2 %0, %1, %2, %0;" : "+l"(acc2[1]) : "l"(k0.y), "l"(m0));
                unsigned long long m1 = pack2(s_Ms[(e + 1) * 64 + a]);
                ulonglong2 k1 = *(const ulonglong2*)(s_E + (e + 1) * 64 + e0);
                asm("fma.rn.f32x2 %0, %1, %2, %0;" : "+l"(bcc2[0]) : "l"(k1.x), "l"(m1));
                asm("fma.rn.f32x2 %0, %1, %2, %0;" : "+l"(bcc2[1]) : "l"(k1.y), "l"(m1));
            }
            float asv = s_as[a];
            float m[4] = {lo2(acc2[0]) + lo2(bcc2[0]), hi2(acc2[0]) + hi2(bcc2[0]),
                          lo2(acc2[1]) + lo2(bcc2[1]), hi2(acc2[1]) + hi2(bcc2[1])};
            float part = 0.f;
#pragma unroll
            for (int j = 0; j < 4; j++) {
                m[j] = (m[j] + s_b2[e0 + j] * asv) * invN;
                part += s_tis[e0 + j] * m[j];
            }
            s_tmp[eg * 64 + a] = part;
            __syncthreads();
#pragma unroll
            for (int j = 0; j < 4; j++) s_Ms[(e0 + j) * 64 + a] += m[j];
            if (tid < 64) {
                float d = 0.f;
#pragma unroll
                for (int g = 0; g < 16; g++) d += s_tmp[g * 64 + tid];
                s_as[tid] += d;
            }
            __syncthreads();
        }
    }
    for (int i = tid; i < 4096; i += 1024) g_Msum[b * 4096 + i] = s_Ms[i];
}

// ---------------- 7: final: att rows, ol, max (32 rows/block) ------------------
__global__ void __launch_bounds__(128) k_final(const int* __restrict__ ops,
                                               const float* __restrict__ cIn,
                                               const float* __restrict__ att_init) {
    int b = blockIdx.y;
    int ag = threadIdx.x;
    int ny = threadIdx.y;
    int tid = ny * 16 + ag;
    __shared__ float s_Ms[4096], s_meta[768], s_ai[64];
    __shared__ float s_ti[8][64], s_pr[8][16];
    __shared__ int s_opf[12];
    for (int i = tid; i < 4096; i += 128) s_Ms[i] = g_Msum[b * 4096 + i];
    for (int i = tid; i < 768; i += 128) s_meta[i] = g_meta[b * 768 + i];
    if (tid < 64) s_ai[tid] = att_init[tid];
    if (tid < 12) s_opf[tid] = ops[b * L_ + tid];
    int base = blockIdx.x * 32;
    for (int g4 = 0; g4 < 4; g4++) {
        int n0 = base + g4 * 8;
        __syncthreads();
        for (int i = tid; i < 512; i += 128) {
            int r = i >> 6, e = i & 63;
            int n = n0 + r;
            const float* row = (n < C_) ? cIn + (size_t)n * 64
                                        : g_objIn + (size_t)(b * O_ + n - C_) * 64;
            s_ti[r][e] = row[e];
        }
        {
            int r = tid >> 4, c = tid & 15;
            s_pr[r][c] = g_proj[(size_t)(b * N_ + n0 + r) * 16 + c];
        }
        __syncthreads();
        int n = n0 + ny;
        int a0 = ag * 4;
        float v0 = s_ai[a0], v1 = s_ai[a0 + 1], v2 = s_ai[a0 + 2], v3 = s_ai[a0 + 3];
#pragma unroll
        for (int s = 0; s < 12; s++)
            if (s_opf[s] == 1) {
                float pp = s_pr[ny][s];
                v0 += pp * s_meta[s * 64 + a0];
                v1 += pp * s_meta[s * 64 + a0 + 1];
                v2 += pp * s_meta[s * 64 + a0 + 2];
                v3 += pp * s_meta[s * 64 + a0 + 3];
            }
        const float4* Ms4 = (const float4*)s_Ms;
#pragma unroll
        for (int e = 0; e < 64; e++) {
            float ti = s_ti[ny][e];
            float4 m = Ms4[e * 16 + ag];
            v0 += ti * m.x; v1 += ti * m.y; v2 += ti * m.z; v3 += ti * m.w;
        }
        float sq = v0 * v0 + v1 * v1 + v2 * v2 + v3 * v3;
#pragma unroll
        for (int o = 8; o > 0; o >>= 1) sq += __shfl_xor_sync(0xffffffffu, sq, o);
        if (ag == 0) {
            float ol = sq * (1.0f / 64.0f);
            g_ol[b * N_ + n] = ol;
            atomicMax(&g_olmax[b], __float_as_int(ol));  // ol >= 0
        }
    }
}

// ---------------- 8: softmax ----------------------------------------------------
__global__ void __launch_bounds__(1024) k_soft(float* __restrict__ out) {
    int b = blockIdx.x;
    int tid = threadIdx.x;
    __shared__ float s_red[1024];
    float mx = __int_as_float(g_olmax[b]);
    float lsum = 0.f;
    for (int n = tid; n < N_; n += 1024) lsum += expf(g_ol[b * N_ + n] - mx);
    s_red[tid] = lsum;
    __syncthreads();
    for (int s = 512; s > 0; s >>= 1) {
        if (tid < s) s_red[tid] += s_red[tid + s];
        __syncthreads();
    }
    float lse = logf(s_red[0]) + mx;
    for (int n = tid; n < N_; n += 1024) out[b * N_ + n] = g_ol[b * N_ + n] - lse;
}

// ---------------- launch --------------------------------------------------------
extern "C" void kernel_launch(void* const* d_in, const int* in_sizes, int n_in,
                              void* d_out, int out_size) {
    const float* class_embIn   = (const float*)d_in[0];
    const float* class_embOut  = (const float*)d_in[1];
    const float* attr_embIn    = (const float*)d_in[2];
    const float* attr_embOut   = (const float*)d_in[3];
    const float* concept_embIn = (const float*)d_in[4];
    const float* concept_embOut= (const float*)d_in[5];
    const float* meta_init     = (const float*)d_in[6];
    const float* attention_init= (const float*)d_in[8];
    const float* axon_w1       = (const float*)d_in[9];
    const float* axon_b1       = (const float*)d_in[10];
    const float* axon_w2       = (const float*)d_in[11];
    const float* axon_b2       = (const float*)d_in[12];
    const float* meta_w1       = (const float*)d_in[13];
    const float* meta_b1       = (const float*)d_in[14];
    const float* meta_w2       = (const float*)d_in[15];
    const float* meta_b2       = (const float*)d_in[16];
    const int*   program_ops   = (const int*)d_in[17];
    const int*   program_args  = (const int*)d_in[18];
    const int*   gt_classes    = (const int*)d_in[19];
    const int*   gt_attributes = (const int*)d_in[20];
    float* out = (float*)d_out;

    cudaFuncSetAttribute(k_meta, cudaFuncAttributeMaxDynamicSharedMemorySize,
                         49152 * (int)sizeof(float));  // 192 KB

    k_pre<<<345, 256>>>(class_embIn, class_embOut, attr_embIn, attr_embOut,   // 1
                        gt_classes, gt_attributes, axon_w1, concept_embOut,
                        program_args);
    k_meta<<<B_, 512, 49152 * sizeof(float)>>>(meta_init, meta_w1, meta_b1,   // 2
                                               meta_w2, meta_b2, program_ops);
    k_proj<<<dim3(N_ / 8, B_), 256>>>(concept_embOut, concept_embIn);         // 3
    k_D<<<dim3(N_ / 64, L_, B_), 256>>>(program_ops, concept_embIn,           // 4
                                        axon_w1, axon_b1);
    k_E<<<dim3(L_, B_), 256>>>(program_ops, axon_w2);                         // 5
    k_rec<<<B_, 1024>>>(program_ops, axon_b2, attention_init);                // 6
    k_final<<<dim3(N_ / 32, B_), dim3(16, 8)>>>(program_ops, concept_embIn,   // 7
                                                attention_init);
    k_soft<<<B_, 1024>>>(out);                                                // 8
}

// round 13
// speedup vs baseline: 1.2498x; 1.0294x over previous
#include <cuda_runtime.h>

// Problem constants
constexpr int B_ = 8, L_ = 12, C_ = 4096, O_ = 128, N_ = 4224;
constexpr int E_ = 64, A_ = 64, H_ = 256;
constexpr int DCOLS = 80;  // X cols: 0..63 tIn, 64..75 proj_s, 76 = ones, 77..79 pad

// ---------------- scratch (device globals) ----------------------------------
__device__ __align__(16) float g_objIn[B_ * O_ * E_];
__device__ __align__(16) float g_objOut[B_ * O_ * E_];
__device__ __align__(16) float g_T1c[C_ * H_];
__device__ __align__(16) float g_T1o[B_ * O_ * H_];
__device__ __align__(16) float g_meta[B_ * L_ * A_];
__device__ __align__(16) float g_arg[B_ * L_ * E_];
__device__ __align__(16) float g_proj[B_ * N_ * 16];
__device__ __align__(16) float g_psum[B_ * 16];
__device__ __align__(16) float g_tInsum[B_ * E_];
__device__ __align__(16) float g_D[B_ * L_ * H_ * DCOLS];   // [bt][h][c]
__device__ __align__(16) float g_E[B_ * L_ * DCOLS * 64];   // [bt][c][e'] (transposed)
__device__ __align__(16) float g_Msum[B_ * E_ * A_];
__device__ __align__(16) float g_ol[B_ * N_];
__device__ int g_olmax[B_];

__device__ __forceinline__ unsigned long long pack2(float v) {
    unsigned int b = __float_as_uint(v);
    return ((unsigned long long)b << 32) | b;
}
__device__ __forceinline__ float lo2(unsigned long long v) {
    return __uint_as_float((unsigned)(v & 0xffffffffULL));
}
__device__ __forceinline__ float hi2(unsigned long long v) {
    return __uint_as_float((unsigned)(v >> 32));
}

// ---------------- 1: fused precompute: T1c | objT1o | zero | arg gather -------
// blocks: [0,256) T1c, [256,320) objT1o, [320,344) zero, [344] arg gather
__global__ void __launch_bounds__(256) k_pre(
    const float* __restrict__ clsIn, const float* __restrict__ clsOut,
    const float* __restrict__ atIn, const float* __restrict__ atOut,
    const int* __restrict__ gt_cls, const int* __restrict__ gt_attr,
    const float* __restrict__ w1, const float* __restrict__ cOut,
    const int* __restrict__ args) {
    int bx = blockIdx.x;
    int tid = threadIdx.x;
    __shared__ float s_emb[1024];
    __shared__ float s_w[4096];

    if (bx < 256) {
        int n0 = bx * 16;
        for (int i = tid; i < 1024; i += 256) s_emb[i] = cOut[n0 * E_ + i];
        float acc[16];
#pragma unroll
        for (int r = 0; r < 16; r++) acc[r] = 0.f;
        for (int ch = 0; ch < 4; ch++) {
            __syncthreads();
            {
                const float4* src = (const float4*)(w1 + ch * 16 * H_);
                float4* dst = (float4*)s_w;
                for (int i = tid; i < 1024; i += 256) dst[i] = src[i];
            }
            __syncthreads();
#pragma unroll
            for (int e = 0; e < 16; e++) {
                float w = s_w[e * H_ + tid];
                int ge = ch * 16 + e;
#pragma unroll
                for (int r = 0; r < 16; r++) acc[r] += s_emb[r * 64 + ge] * w;
            }
        }
#pragma unroll
        for (int r = 0; r < 16; r++) g_T1c[(n0 + r) * H_ + tid] = acc[r];
    } else if (bx < 320) {
        int idx = bx - 256;
        int b = idx >> 3;
        int o0 = (idx & 7) * 16;
        for (int i = tid; i < 1024; i += 256) {
            int r = i >> 6, e = i & 63;
            int o = o0 + r;
            int cls = gt_cls[b * O_ + o];
            float vi = clsIn[cls * E_ + e];
            float vo = clsOut[cls * E_ + e];
#pragma unroll
            for (int k = 0; k < 8; k++) {
                int at = gt_attr[(b * O_ + o) * 8 + k];
                vi += atIn[at * E_ + e];
                vo += atOut[at * E_ + e];
            }
            g_objIn[(b * O_ + o) * E_ + e] = vi;
            g_objOut[(b * O_ + o) * E_ + e] = vo;
            s_emb[i] = vo;
        }
        float acc[16];
#pragma unroll
        for (int r = 0; r < 16; r++) acc[r] = 0.f;
        for (int ch = 0; ch < 4; ch++) {
            __syncthreads();
            {
                const float4* src = (const float4*)(w1 + ch * 16 * H_);
                float4* dst = (float4*)s_w;
                for (int i = tid; i < 1024; i += 256) dst[i] = src[i];
            }
            __syncthreads();
#pragma unroll
            for (int e = 0; e < 16; e++) {
                float w = s_w[e * H_ + tid];
                int ge = ch * 16 + e;
#pragma unroll
                for (int r = 0; r < 16; r++) acc[r] += s_emb[r * 64 + ge] * w;
            }
        }
#pragma unroll
        for (int r = 0; r < 16; r++) g_T1o[(b * O_ + o0 + r) * H_ + tid] = acc[r];
    } else if (bx < 344) {
        int i = (bx - 320) * 256 + tid;   // 0..6143
        float4 z = make_float4(0.f, 0.f, 0.f, 0.f);
        float4* d4 = (float4*)g_D;
#pragma unroll
        for (int j = 0; j < 80; j++) d4[j * 6144 + i] = z;
        if (bx == 320) {
            if (tid < 128) g_psum[tid] = 0.f;
            g_tInsum[tid] = 0.f;
            g_tInsum[256 + tid] = 0.f;
            if (tid < 8) g_olmax[tid] = 0;
        }
    } else {
        for (int i = tid; i < B_ * L_ * E_; i += 256) {
            int bt = i >> 6, e = i & 63;
            g_arg[i] = cOut[args[bt] * E_ + e];
        }
    }
}

// ---------------- 2: meta recurrence (512 threads, split-K) -------------------
__global__ void __launch_bounds__(512) k_meta(
    const float* __restrict__ meta_init,
    const float* __restrict__ mw1, const float* __restrict__ mb1,
    const float* __restrict__ mw2, const float* __restrict__ mb2,
    const int* __restrict__ ops) {
    extern __shared__ float dsm[];
    float* s_w1 = dsm;             // 128*256 (full meta_w1)
    float* s_w2 = dsm + 32768;     // 256*64
    __shared__ float s_in[128];    // [meta(64) | arg(64)]
    __shared__ float s_h[256], s_pre[512], s_part[512];
    int b = blockIdx.x;
    int tid = threadIdx.x;
    {
        const float4* w1_4 = (const float4*)mw1;
        float4* d1 = (float4*)s_w1;
        for (int i = tid; i < 8192; i += 512) d1[i] = w1_4[i];
        const float4* w2_4 = (const float4*)mw2;
        float4* d2 = (float4*)s_w2;
        for (int i = tid; i < 4096; i += 512) d2[i] = w2_4[i];
    }
    float r_mb1 = (tid < 256) ? mb1[tid] : 0.f;
    float r_mb2 = (tid < 64) ? mb2[tid] : 0.f;
    if (tid < 64) s_in[tid] = meta_init[tid];
    __syncthreads();
    int h = tid & 255, half = tid >> 8;
    int a = tid & 63, pq = tid >> 6;
    for (int t = 0; t < L_; t++) {
        if (tid < 64) s_in[64 + tid] = g_arg[(b * L_ + t) * E_ + tid];
        __syncthreads();
        {
            int base = half * 64;
            float p0 = 0.f, p1 = 0.f, p2 = 0.f, p3 = 0.f;
#pragma unroll
            for (int k = 0; k < 64; k += 4) {
                p0 += s_in[base + k] * s_w1[(base + k) * H_ + h];
                p1 += s_in[base + k + 1] * s_w1[(base + k + 1) * H_ + h];
                p2 += s_in[base + k + 2] * s_w1[(base + k + 2) * H_ + h];
                p3 += s_in[base + k + 3] * s_w1[(base + k + 3) * H_ + h];
            }
            s_pre[tid] = (p0 + p1) + (p2 + p3);
        }
        __syncthreads();
        if (tid < 256) s_h[tid] = fmaxf(r_mb1 + s_pre[tid] + s_pre[256 + tid], 0.f);
        __syncthreads();
        {
            int base = pq * 32;
            float q0 = 0.f, q1 = 0.f;
#pragma unroll
            for (int k = 0; k < 32; k += 2) {
                q0 += s_h[base + k] * s_w2[(base + k) * A_ + a];
                q1 += s_h[base + k + 1] * s_w2[(base + k + 1) * A_ + a];
            }
            s_part[tid] = q0 + q1;
        }
        __syncthreads();
        if (tid < 64) {
            float nm = r_mb2;
#pragma unroll
            for (int g = 0; g < 8; g++) nm += s_part[g * 64 + tid];
            float nv = (ops[b * L_ + t] == 0) ? nm : s_in[tid];
            s_in[tid] = nv;
            g_meta[(b * L_ + t) * A_ + tid] = nv;
        }
        __syncthreads();
    }
}

// ---------------- 3: proj (tinsum fused) --------------------------------------
__global__ void __launch_bounds__(256) k_proj(const float* __restrict__ cOut,
                                              const float* __restrict__ cIn) {
    int b = blockIdx.y;
    int tid = threadIdx.x;
    int w = tid >> 5, lane = tid & 31;
    __shared__ float s_arg[768];
    __shared__ float s_p[8][16];
    __shared__ float s_tin[64];
    if (tid < 64) s_tin[tid] = 0.f;
    for (int i = tid; i < 768; i += 256) s_arg[i] = g_arg[b * 768 + i];
    __syncthreads();
    int n = blockIdx.x * 8 + w;
    const float* rowO = (n < C_) ? cOut + (size_t)n * 64
                                 : g_objOut + (size_t)(b * O_ + n - C_) * 64;
    const float* rowI = (n < C_) ? cIn + (size_t)n * 64
                                 : g_objIn + (size_t)(b * O_ + n - C_) * 64;
    float x0 = rowO[lane], x1 = rowO[lane + 32];
    atomicAdd(&s_tin[lane], rowI[lane]);
    atomicAdd(&s_tin[lane + 32], rowI[lane + 32]);
#pragma unroll
    for (int s = 0; s < 12; s++) {
        float p = x0 * s_arg[s * 64 + lane] + x1 * s_arg[s * 64 + 32 + lane];
#pragma unroll
        for (int o = 16; o > 0; o >>= 1) p += __shfl_xor_sync(0xffffffffu, p, o);
        if (lane == 0) s_p[w][s] = p * (1.0f / 64.0f);
    }
    __syncwarp();
    if (lane < 16) {
        float v = (lane < 12) ? s_p[w][lane] : ((lane == 12) ? 1.0f : 0.0f);
        g_proj[(size_t)(b * N_ + n) * 16 + lane] = v;
        if (lane < 12) atomicAdd(&g_psum[b * 16 + lane], v);
    }
    __syncthreads();
    if (tid < 64) atomicAdd(&g_tInsum[b * 64 + tid], s_tin[tid]);
}

// ---------------- 4: big GEMM D_t = Hrel_t^T @ [tIn | proj | 1] ----------------
// 256 threads, tile 4h x 20c (hg = tid&63 -> h=hg*4, cg = tid>>6 -> c=cg*20).
// One 64-n tile per block. T1 staged through smem in 16-n chunks (coalesced,
// deduplicated), relu(T1+u) applied at staging time.
__global__ void __launch_bounds__(256, 2) k_D(const int* __restrict__ ops,
                                              const float* __restrict__ cIn,
                                              const float* __restrict__ aw1,
                                              const float* __restrict__ ab1) {
    int t = blockIdx.y, b = blockIdx.z;
    if (ops[b * L_ + t] != 2) return;
    int tid = threadIdx.x;
    int hg = tid & 63;        // h base = hg*4
    int cg = tid >> 6;        // c base = cg*20
    __shared__ float s_mt[64];
    __shared__ __align__(16) float s_u[256];
    __shared__ __align__(16) float s_X[64 * 80];
    __shared__ __align__(16) float s_T1[16 * 256];   // one 16-n chunk of relu(T1+u)
    if (tid < 64) s_mt[tid] = g_meta[(b * L_ + t) * A_ + tid];
    __syncthreads();
    {   // u[h] cooperative: thread tid computes h = tid
        float u0 = 0.f, u1 = 0.f, u2 = 0.f, u3 = 0.f;
#pragma unroll 4
        for (int a = 0; a < 64; a += 4) {
            u0 += s_mt[a] * __ldg(&aw1[(64 + a) * H_ + tid]);
            u1 += s_mt[a + 1] * __ldg(&aw1[(65 + a) * H_ + tid]);
            u2 += s_mt[a + 2] * __ldg(&aw1[(66 + a) * H_ + tid]);
            u3 += s_mt[a + 3] * __ldg(&aw1[(67 + a) * H_ + tid]);
        }
        s_u[tid] = ab1[tid] + ((u0 + u1) + (u2 + u3));
    }

    int n0 = blockIdx.x * 64;
    bool isC = (n0 < C_);   // whole 64-tile is one side (C_ 64-aligned)
    {   // stage X tile
        const float4* srcb = isC
            ? (const float4*)cIn + (size_t)n0 * 16
            : (const float4*)g_objIn + (size_t)(b * O_ + n0 - C_) * 16;
        float4* dst = (float4*)s_X;
        for (int i = tid; i < 1024; i += 256) {
            int r = i >> 4, c = i & 15;
            dst[r * 20 + c] = srcb[r * 16 + c];
        }
        {
            int r = tid >> 2, c = tid & 3;
            dst[r * 20 + 16 + c] =
                ((const float4*)g_proj)[(size_t)(b * N_ + n0 + r) * 4 + c];
        }
    }
    // T1 source for this tile: row n has 64 float4; thread loads rows
    // {cg, cg+4, cg+8, cg+12} of each 16-n chunk at float4-column hg.
    const float4* t1base = (const float4*)(isC ? g_T1c + (size_t)n0 * H_
                                               : g_T1o + (size_t)(b * O_ + n0 - C_) * H_);
    float4 pre[4];
#pragma unroll
    for (int k = 0; k < 4; k++) pre[k] = t1base[(cg + k * 4) * 64 + hg];

    __syncthreads();   // X + u staged
    float4 uv = *(const float4*)(s_u + hg * 4);

    unsigned long long acc[40];   // [i=h-sub][j=0..9] -> acc[i*10+j]
#pragma unroll
    for (int j = 0; j < 40; j++) acc[j] = 0ULL;

    float4* st4 = (float4*)s_T1;
    for (int ch = 0; ch < 4; ch++) {
        if (ch) __syncthreads();            // previous chunk consumed
#pragma unroll
        for (int k = 0; k < 4; k++) {
            float4 v = pre[k];
            v.x = fmaxf(v.x + uv.x, 0.f);
            v.y = fmaxf(v.y + uv.y, 0.f);
            v.z = fmaxf(v.z + uv.z, 0.f);
            v.w = fmaxf(v.w + uv.w, 0.f);
            st4[(cg + k * 4) * 64 + hg] = v;
        }
        __syncthreads();                    // chunk visible
        if (ch < 3) {                       // issue next chunk's loads early
            const float4* nb = t1base + (ch + 1) * 16 * 64;
#pragma unroll
            for (int k = 0; k < 4; k++) pre[k] = nb[(cg + k * 4) * 64 + hg];
        }
        int nlo = ch * 16;
#pragma unroll 4
        for (int nl = 0; nl < 16; nl++) {
            float4 hv = st4[nl * 64 + hg];
            unsigned long long hv2_0 = pack2(hv.x);
            unsigned long long hv2_1 = pack2(hv.y);
            unsigned long long hv2_2 = pack2(hv.z);
            unsigned long long hv2_3 = pack2(hv.w);
            const ulonglong2* xr = (const ulonglong2*)(s_X + (nlo + nl) * 80 + cg * 20);
#pragma unroll
            for (int j = 0; j < 5; j++) {
                ulonglong2 p = xr[j];
                asm("fma.rn.f32x2 %0, %1, %2, %0;" : "+l"(acc[0 * 10 + 2 * j]) : "l"(hv2_0), "l"(p.x));
                asm("fma.rn.f32x2 %0, %1, %2, %0;" : "+l"(acc[0 * 10 + 2 * j + 1]) : "l"(hv2_0), "l"(p.y));
                asm("fma.rn.f32x2 %0, %1, %2, %0;" : "+l"(acc[1 * 10 + 2 * j]) : "l"(hv2_1), "l"(p.x));
                asm("fma.rn.f32x2 %0, %1, %2, %0;" : "+l"(acc[1 * 10 + 2 * j + 1]) : "l"(hv2_1), "l"(p.y));
                asm("fma.rn.f32x2 %0, %1, %2, %0;" : "+l"(acc[2 * 10 + 2 * j]) : "l"(hv2_2), "l"(p.x));
                asm("fma.rn.f32x2 %0, %1, %2, %0;" : "+l"(acc[2 * 10 + 2 * j + 1]) : "l"(hv2_2), "l"(p.y));
                asm("fma.rn.f32x2 %0, %1, %2, %0;" : "+l"(acc[3 * 10 + 2 * j]) : "l"(hv2_3), "l"(p.x));
                asm("fma.rn.f32x2 %0, %1, %2, %0;" : "+l"(acc[3 * 10 + 2 * j + 1]) : "l"(hv2_3), "l"(p.y));
            }
        }
    }

#pragma unroll
    for (int i = 0; i < 4; i++) {
        float* dp = g_D + ((size_t)(b * L_ + t) * H_ + hg * 4 + i) * DCOLS + cg * 20;
#pragma unroll
        for (int j = 0; j < 10; j++) {
            asm volatile("red.global.add.v2.f32 [%0], {%1, %2};"
                         :: "l"(dp + 2 * j), "f"(lo2(acc[i * 10 + j])),
                            "f"(hi2(acc[i * 10 + j])) : "memory");
        }
    }
}

// ---------------- 5: k_E: E_t = W2^T @ D_t  (stored transposed [c][e']) --------
__global__ void __launch_bounds__(256) k_E(const int* __restrict__ ops,
                                           const float* __restrict__ w2) {
    int t = blockIdx.x, b = blockIdx.y;
    if (ops[b * L_ + t] != 2) return;
    int tid = threadIdx.x;
    int ep = tid & 63;
    int cq = tid >> 6;
    __shared__ __align__(16) float s_D[64 * 80];
    __shared__ __align__(16) float s_w2[64 * 64];
    unsigned long long acc[10];
#pragma unroll
    for (int j = 0; j < 10; j++) acc[j] = 0ULL;
    size_t dbase = (size_t)(b * L_ + t) * H_ * DCOLS;
    for (int ch = 0; ch < 4; ch++) {
        __syncthreads();
        {
            const float4* src = (const float4*)(g_D + dbase + ch * 64 * DCOLS);
            float4* dst = (float4*)s_D;
            for (int i = tid; i < 1280; i += 256) dst[i] = src[i];
            const float4* wsrc = (const float4*)(w2 + ch * 64 * 64);
            float4* wdst = (float4*)s_w2;
            for (int i = tid; i < 1024; i += 256) wdst[i] = wsrc[i];
        }
        __syncthreads();
        const unsigned long long* D2 = (const unsigned long long*)s_D;
#pragma unroll 8
        for (int hh = 0; hh < 64; hh++) {
            unsigned long long w2v = pack2(s_w2[hh * 64 + ep]);
            const unsigned long long* drow = D2 + hh * 40 + cq * 10;
#pragma unroll
            for (int j = 0; j < 10; j++) {
                asm("fma.rn.f32x2 %0, %1, %2, %0;" : "+l"(acc[j]) : "l"(w2v), "l"(drow[j]));
            }
        }
    }
    float* eb = g_E + (size_t)(b * L_ + t) * DCOLS * 64;
#pragma unroll
    for (int j = 0; j < 10; j++) {
        int c = cq * 20 + 2 * j;
        eb[c * 64 + ep] = lo2(acc[j]);
        eb[(c + 1) * 64 + ep] = hi2(acc[j]);
    }
}

// ---------------- 6: tiny serial recurrence: Msum, attsum ----------------------
__global__ void __launch_bounds__(1024) k_rec(const int* __restrict__ ops,
                                              const float* __restrict__ b2,
                                              const float* __restrict__ att_init) {
    __shared__ __align__(16) float s_Ms[4096];
    __shared__ __align__(16) float s_E[5120];
    __shared__ float s_meta[768], s_tmp[1024];
    __shared__ float s_as[64], s_ai[64], s_tis[64], s_b2[64], s_ps[12];
    __shared__ int s_op[12];
    int b = blockIdx.x, tid = threadIdx.x;
    for (int i = tid; i < 4096; i += 1024) s_Ms[i] = 0.f;
    if (tid < 768) s_meta[tid] = g_meta[b * 768 + tid];
    if (tid < 64) {
        s_ai[tid] = att_init[tid];
        s_as[tid] = (float)N_ * att_init[tid];
        s_tis[tid] = g_tInsum[b * 64 + tid];
        s_b2[tid] = b2[tid];
    }
    if (tid < 12) { s_op[tid] = ops[b * L_ + tid]; s_ps[tid] = g_psum[b * 16 + tid]; }
    __syncthreads();
    const float invN = 1.0f / (float)N_;
    int a = tid & 63, eg = tid >> 6;
    int e0 = eg * 4;
    for (int t = 0; t < L_; t++) {
        int op = s_op[t];
        if (op == 1) {
            if (tid < 64) s_as[tid] += s_ps[t] * s_meta[t * 64 + tid];
            __syncthreads();
        } else if (op == 2) {
            const float* esrc = g_E + (size_t)(b * L_ + t) * 5120;
            for (int i = tid; i < 5120; i += 1024) s_E[i] = esrc[i];
            __syncthreads();
            unsigned long long ai2 = pack2(s_ai[a]);
            unsigned long long acc2[2], bcc2[2];
            {
                ulonglong2 es = *(const ulonglong2*)(s_E + 76 * 64 + e0);
                acc2[0] = 0ULL; acc2[1] = 0ULL; bcc2[0] = 0ULL; bcc2[1] = 0ULL;
                asm("fma.rn.f32x2 %0, %1, %2, %0;" : "+l"(acc2[0]) : "l"(es.x), "l"(ai2));
                asm("fma.rn.f32x2 %0, %1, %2, %0;" : "+l"(acc2[1]) : "l"(es.y), "l"(ai2));
            }
            for (int s = 0; s < t; s++)
                if (s_op[s] == 1) {
                    unsigned long long mv = pack2(s_meta[s * 64 + a]);
                    ulonglong2 er = *(const ulonglong2*)(s_E + (64 + s) * 64 + e0);
                    asm("fma.rn.f32x2 %0, %1, %2, %0;" : "+l"(acc2[0]) : "l"(er.x), "l"(mv));
                    asm("fma.rn.f32x2 %0, %1, %2, %0;" : "+l"(acc2[1]) : "l"(er.y), "l"(mv));
                }
#pragma unroll 4
            for (int e = 0; e < 64; e += 2) {
                unsigned long long m0 = pack2(s_Ms[e * 64 + a]);
                ulonglong2 k0 = *(const ulonglong2*)(s_E + e * 64 + e0);
                asm("fma.rn.f32x2 %0, %1, %2, %0;" : "+l"(acc2[0]) : "l"(k0.x), "l"(m0));
                asm("fma.rn.f32x2 %0, %1, %2, %0;" : "+l"(acc2[1]) : "l"(k0.y), "l"(m0));
                unsigned long long m1 = pack2(s_Ms[(e + 1) * 64 + a]);
                ulonglong2 k1 = *(const ulonglong2*)(s_E + (e + 1) * 64 + e0);
                asm("fma.rn.f32x2 %0, %1, %2, %0;" : "+l"(bcc2[0]) : "l"(k1.x), "l"(m1));
                asm("fma.rn.f32x2 %0, %1, %2, %0;" : "+l"(bcc2[1]) : "l"(k1.y), "l"(m1));
            }
            float asv = s_as[a];
            float m[4] = {lo2(acc2[0]) + lo2(bcc2[0]), hi2(acc2[0]) + hi2(bcc2[0]),
                          lo2(acc2[1]) + lo2(bcc2[1]), hi2(acc2[1]) + hi2(bcc2[1])};
            float part = 0.f;
#pragma unroll
            for (int j = 0; j < 4; j++) {
                m[j] = (m[j] + s_b2[e0 + j] * asv) * invN;
                part += s_tis[e0 + j] * m[j];
            }
            s_tmp[eg * 64 + a] = part;
            __syncthreads();
#pragma unroll
            for (int j = 0; j < 4; j++) s_Ms[(e0 + j) * 64 + a] += m[j];
            if (tid < 64) {
                float d = 0.f;
#pragma unroll
                for (int g = 0; g < 16; g++) d += s_tmp[g * 64 + tid];
                s_as[tid] += d;
            }
            __syncthreads();
        }
    }
    for (int i = tid; i < 4096; i += 1024) g_Msum[b * 4096 + i] = s_Ms[i];
}

// ---------------- 7: final: att rows, ol, max (32 rows/block) ------------------
__global__ void __launch_bounds__(128) k_final(const int* __restrict__ ops,
                                               const float* __restrict__ cIn,
                                               const float* __restrict__ att_init) {
    int b = blockIdx.y;
    int ag = threadIdx.x;
    int ny = threadIdx.y;
    int tid = ny * 16 + ag;
    __shared__ float s_Ms[4096], s_meta[768], s_ai[64];
    __shared__ float s_ti[8][64], s_pr[8][16];
    __shared__ int s_opf[12];
    for (int i = tid; i < 4096; i += 128) s_Ms[i] = g_Msum[b * 4096 + i];
    for (int i = tid; i < 768; i += 128) s_meta[i] = g_meta[b * 768 + i];
    if (tid < 64) s_ai[tid] = att_init[tid];
    if (tid < 12) s_opf[tid] = ops[b * L_ + tid];
    int base = blockIdx.x * 32;
    for (int g4 = 0; g4 < 4; g4++) {
        int n0 = base + g4 * 8;
        __syncthreads();
        for (int i = tid; i < 512; i += 128) {
            int r = i >> 6, e = i & 63;
            int n = n0 + r;
            const float* row = (n < C_) ? cIn + (size_t)n * 64
                                        : g_objIn + (size_t)(b * O_ + n - C_) * 64;
            s_ti[r][e] = row[e];
        }
        {
            int r = tid >> 4, c = tid & 15;
            s_pr[r][c] = g_proj[(size_t)(b * N_ + n0 + r) * 16 + c];
        }
        __syncthreads();
        int n = n0 + ny;
        int a0 = ag * 4;
        float v0 = s_ai[a0], v1 = s_ai[a0 + 1], v2 = s_ai[a0 + 2], v3 = s_ai[a0 + 3];
#pragma unroll
        for (int s = 0; s < 12; s++)
            if (s_opf[s] == 1) {
                float pp = s_pr[ny][s];
                v0 += pp * s_meta[s * 64 + a0];
                v1 += pp * s_meta[s * 64 + a0 + 1];
                v2 += pp * s_meta[s * 64 + a0 + 2];
                v3 += pp * s_meta[s * 64 + a0 + 3];
            }
        const float4* Ms4 = (const float4*)s_Ms;
#pragma unroll
        for (int e = 0; e < 64; e++) {
            float ti = s_ti[ny][e];
            float4 m = Ms4[e * 16 + ag];
            v0 += ti * m.x; v1 += ti * m.y; v2 += ti * m.z; v3 += ti * m.w;
        }
        float sq = v0 * v0 + v1 * v1 + v2 * v2 + v3 * v3;
#pragma unroll
        for (int o = 8; o > 0; o >>= 1) sq += __shfl_xor_sync(0xffffffffu, sq, o);
        if (ag == 0) {
            float ol = sq * (1.0f / 64.0f);
            g_ol[b * N_ + n] = ol;
            atomicMax(&g_olmax[b], __float_as_int(ol));  // ol >= 0
        }
    }
}

// ---------------- 8: softmax ----------------------------------------------------
__global__ void __launch_bounds__(1024) k_soft(float* __restrict__ out) {
    int b = blockIdx.x;
    int tid = threadIdx.x;
    __shared__ float s_red[1024];
    float mx = __int_as_float(g_olmax[b]);
    float lsum = 0.f;
    for (int n = tid; n < N_; n += 1024) lsum += expf(g_ol[b * N_ + n] - mx);
    s_red[tid] = lsum;
    __syncthreads();
    for (int s = 512; s > 0; s >>= 1) {
        if (tid < s) s_red[tid] += s_red[tid + s];
        __syncthreads();
    }
    float lse = logf(s_red[0]) + mx;
    for (int n = tid; n < N_; n += 1024) out[b * N_ + n] = g_ol[b * N_ + n] - lse;
}

// ---------------- launch --------------------------------------------------------
extern "C" void kernel_launch(void* const* d_in, const int* in_sizes, int n_in,
                              void* d_out, int out_size) {
    const float* class_embIn   = (const float*)d_in[0];
    const float* class_embOut  = (const float*)d_in[1];
    const float* attr_embIn    = (const float*)d_in[2];
    const float* attr_embOut   = (const float*)d_in[3];
    const float* concept_embIn = (const float*)d_in[4];
    const float* concept_embOut= (const float*)d_in[5];
    const float* meta_init     = (const float*)d_in[6];
    const float* attention_init= (const float*)d_in[8];
    const float* axon_w1       = (const float*)d_in[9];
    const float* axon_b1       = (const float*)d_in[10];
    const float* axon_w2       = (const float*)d_in[11];
    const float* axon_b2       = (const float*)d_in[12];
    const float* meta_w1       = (const float*)d_in[13];
    const float* meta_b1       = (const float*)d_in[14];
    const float* meta_w2       = (const float*)d_in[15];
    const float* meta_b2       = (const float*)d_in[16];
    const int*   program_ops   = (const int*)d_in[17];
    const int*   program_args  = (const int*)d_in[18];
    const int*   gt_classes    = (const int*)d_in[19];
    const int*   gt_attributes = (const int*)d_in[20];
    float* out = (float*)d_out;

    cudaFuncSetAttribute(k_meta, cudaFuncAttributeMaxDynamicSharedMemorySize,
                         49152 * (int)sizeof(float));  // 192 KB

    k_pre<<<345, 256>>>(class_embIn, class_embOut, attr_embIn, attr_embOut,   // 1
                        gt_classes, gt_attributes, axon_w1, concept_embOut,
                        program_args);
    k_meta<<<B_, 512, 49152 * sizeof(float)>>>(meta_init, meta_w1, meta_b1,   // 2
                                               meta_w2, meta_b2, program_ops);
    k_proj<<<dim3(N_ / 8, B_), 256>>>(concept_embOut, concept_embIn);         // 3
    k_D<<<dim3(N_ / 64, L_, B_), 256>>>(program_ops, concept_embIn,           // 4
                                        axon_w1, axon_b1);
    k_E<<<dim3(L_, B_), 256>>>(program_ops, axon_w2);                         // 5
    k_rec<<<B_, 1024>>>(program_ops, axon_b2, attention_init);                // 6
    k_final<<<dim3(N_ / 32, B_), dim3(16, 8)>>>(program_ops, concept_embIn,   // 7
                                                attention_init);
    k_soft<<<B_, 1024>>>(out);                                                // 8
}

// round 15
// speedup vs baseline: 1.6695x; 1.3358x over previous
#include <cuda_runtime.h>

// Problem constants
constexpr int B_ = 8, L_ = 12, C_ = 4096, O_ = 128, N_ = 4224;
constexpr int E_ = 64, A_ = 64, H_ = 256;
constexpr int DCOLS = 80;
constexpr int NTILES = N_ / 64;        // 66
constexpr int NSPLIT = 11;             // blocks per (b,t); 6 tiles each

// ---------------- scratch (device globals) ----------------------------------
__device__ __align__(16) float g_objIn[B_ * O_ * E_];
__device__ __align__(16) float g_objOut[B_ * O_ * E_];
__device__ __align__(16) float g_T1c[C_ * H_];
__device__ __align__(16) float g_T1o[B_ * O_ * H_];
__device__ __align__(16) float g_meta[B_ * L_ * A_];
__device__ __align__(16) float g_arg[B_ * L_ * E_];
__device__ __align__(16) float g_proj[B_ * N_ * 16];
__device__ __align__(16) float g_psum[B_ * 16];
__device__ __align__(16) float g_tInsum[B_ * E_];
__device__ __align__(16) float g_D[B_ * L_ * H_ * DCOLS];   // [bt][h][c]
__device__ __align__(16) float g_E[B_ * L_ * DCOLS * 64];   // [bt][c][e']
__device__ __align__(16) float g_Msum[B_ * E_ * A_];
__device__ __align__(16) float g_ol[B_ * N_];
__device__ int g_olmax[B_];

__device__ __forceinline__ unsigned long long pack2(float v) {
    unsigned int b = __float_as_uint(v);
    return ((unsigned long long)b << 32) | b;
}
__device__ __forceinline__ float lo2(unsigned long long v) {
    return __uint_as_float((unsigned)(v & 0xffffffffULL));
}
__device__ __forceinline__ float hi2(unsigned long long v) {
    return __uint_as_float((unsigned)(v >> 32));
}
// pack two floats to bf16x2: f1 -> high half, f0 -> low half
__device__ __forceinline__ unsigned cvt_bf16x2(float f1, float f0) {
    unsigned r;
    asm("cvt.rn.satfinite.bf16x2.f32 %0, %1, %2;" : "=r"(r) : "f"(f1), "f"(f0));
    return r;
}
// split packed hi; return lo packed (residual)
__device__ __forceinline__ unsigned bf16_lo(unsigned hi01, float f1, float f0) {
    float f0r = __uint_as_float(hi01 << 16);
    float f1r = __uint_as_float(hi01 & 0xffff0000u);
    return cvt_bf16x2(f1 - f1r, f0 - f0r);
}
__device__ __forceinline__ void mma_bf16(float* d, const unsigned* a, const unsigned* b) {
    asm volatile(
        "mma.sync.aligned.m16n8k16.row.col.f32.bf16.bf16.f32 "
        "{%0,%1,%2,%3}, {%4,%5,%6,%7}, {%8,%9}, {%0,%1,%2,%3};"
        : "+f"(d[0]), "+f"(d[1]), "+f"(d[2]), "+f"(d[3])
        : "r"(a[0]), "r"(a[1]), "r"(a[2]), "r"(a[3]), "r"(b[0]), "r"(b[1]));
}

// ---------------- 1: fused precompute: T1c | objT1o | zero | arg gather -------
__global__ void __launch_bounds__(256) k_pre(
    const float* __restrict__ clsIn, const float* __restrict__ clsOut,
    const float* __restrict__ atIn, const float* __restrict__ atOut,
    const int* __restrict__ gt_cls, const int* __restrict__ gt_attr,
    const float* __restrict__ w1, const float* __restrict__ cOut,
    const int* __restrict__ args) {
    int bx = blockIdx.x;
    int tid = threadIdx.x;
    __shared__ float s_emb[1024];
    __shared__ float s_w[4096];

    if (bx < 256) {
        int n0 = bx * 16;
        for (int i = tid; i < 1024; i += 256) s_emb[i] = cOut[n0 * E_ + i];
        float acc[16];
#pragma unroll
        for (int r = 0; r < 16; r++) acc[r] = 0.f;
        for (int ch = 0; ch < 4; ch++) {
            __syncthreads();
            {
                const float4* src = (const float4*)(w1 + ch * 16 * H_);
                float4* dst = (float4*)s_w;
                for (int i = tid; i < 1024; i += 256) dst[i] = src[i];
            }
            __syncthreads();
#pragma unroll
            for (int e = 0; e < 16; e++) {
                float w = s_w[e * H_ + tid];
                int ge = ch * 16 + e;
#pragma unroll
                for (int r = 0; r < 16; r++) acc[r] += s_emb[r * 64 + ge] * w;
            }
        }
#pragma unroll
        for (int r = 0; r < 16; r++) g_T1c[(n0 + r) * H_ + tid] = acc[r];
    } else if (bx < 320) {
        int idx = bx - 256;
        int b = idx >> 3;
        int o0 = (idx & 7) * 16;
        for (int i = tid; i < 1024; i += 256) {
            int r = i >> 6, e = i & 63;
            int o = o0 + r;
            int cls = gt_cls[b * O_ + o];
            float vi = clsIn[cls * E_ + e];
            float vo = clsOut[cls * E_ + e];
#pragma unroll
            for (int k = 0; k < 8; k++) {
                int at = gt_attr[(b * O_ + o) * 8 + k];
                vi += atIn[at * E_ + e];
                vo += atOut[at * E_ + e];
            }
            g_objIn[(b * O_ + o) * E_ + e] = vi;
            g_objOut[(b * O_ + o) * E_ + e] = vo;
            s_emb[i] = vo;
        }
        float acc[16];
#pragma unroll
        for (int r = 0; r < 16; r++) acc[r] = 0.f;
        for (int ch = 0; ch < 4; ch++) {
            __syncthreads();
            {
                const float4* src = (const float4*)(w1 + ch * 16 * H_);
                float4* dst = (float4*)s_w;
                for (int i = tid; i < 1024; i += 256) dst[i] = src[i];
            }
            __syncthreads();
#pragma unroll
            for (int e = 0; e < 16; e++) {
                float w = s_w[e * H_ + tid];
                int ge = ch * 16 + e;
#pragma unroll
                for (int r = 0; r < 16; r++) acc[r] += s_emb[r * 64 + ge] * w;
            }
        }
#pragma unroll
        for (int r = 0; r < 16; r++) g_T1o[(b * O_ + o0 + r) * H_ + tid] = acc[r];
    } else if (bx < 344) {
        int i = (bx - 320) * 256 + tid;   // 0..6143
        float4 z = make_float4(0.f, 0.f, 0.f, 0.f);
        float4* d4 = (float4*)g_D;
#pragma unroll
        for (int j = 0; j < 80; j++) d4[j * 6144 + i] = z;
        if (bx == 320) {
            if (tid < 128) g_psum[tid] = 0.f;
            g_tInsum[tid] = 0.f;
            g_tInsum[256 + tid] = 0.f;
            if (tid < 8) g_olmax[tid] = 0;
        }
    } else {
        for (int i = tid; i < B_ * L_ * E_; i += 256) {
            int bt = i >> 6, e = i & 63;
            g_arg[i] = cOut[args[bt] * E_ + e];
        }
    }
}

// ---------------- 2: meta recurrence (512 threads, split-K) -------------------
__global__ void __launch_bounds__(512) k_meta(
    const float* __restrict__ meta_init,
    const float* __restrict__ mw1, const float* __restrict__ mb1,
    const float* __restrict__ mw2, const float* __restrict__ mb2,
    const int* __restrict__ ops) {
    extern __shared__ float dsm[];
    float* s_w1 = dsm;
    float* s_w2 = dsm + 32768;
    __shared__ float s_in[128];
    __shared__ float s_h[256], s_pre[512], s_part[512];
    int b = blockIdx.x;
    int tid = threadIdx.x;
    {
        const float4* w1_4 = (const float4*)mw1;
        float4* d1 = (float4*)s_w1;
        for (int i = tid; i < 8192; i += 512) d1[i] = w1_4[i];
        const float4* w2_4 = (const float4*)mw2;
        float4* d2 = (float4*)s_w2;
        for (int i = tid; i < 4096; i += 512) d2[i] = w2_4[i];
    }
    float r_mb1 = (tid < 256) ? mb1[tid] : 0.f;
    float r_mb2 = (tid < 64) ? mb2[tid] : 0.f;
    if (tid < 64) s_in[tid] = meta_init[tid];
    __syncthreads();
    int h = tid & 255, half = tid >> 8;
    int a = tid & 63, pq = tid >> 6;
    for (int t = 0; t < L_; t++) {
        if (tid < 64) s_in[64 + tid] = g_arg[(b * L_ + t) * E_ + tid];
        __syncthreads();
        {
            int base = half * 64;
            float p0 = 0.f, p1 = 0.f, p2 = 0.f, p3 = 0.f;
#pragma unroll
            for (int k = 0; k < 64; k += 4) {
                p0 += s_in[base + k] * s_w1[(base + k) * H_ + h];
                p1 += s_in[base + k + 1] * s_w1[(base + k + 1) * H_ + h];
                p2 += s_in[base + k + 2] * s_w1[(base + k + 2) * H_ + h];
                p3 += s_in[base + k + 3] * s_w1[(base + k + 3) * H_ + h];
            }
            s_pre[tid] = (p0 + p1) + (p2 + p3);
        }
        __syncthreads();
        if (tid < 256) s_h[tid] = fmaxf(r_mb1 + s_pre[tid] + s_pre[256 + tid], 0.f);
        __syncthreads();
        {
            int base = pq * 32;
            float q0 = 0.f, q1 = 0.f;
#pragma unroll
            for (int k = 0; k < 32; k += 2) {
                q0 += s_h[base + k] * s_w2[(base + k) * A_ + a];
                q1 += s_h[base + k + 1] * s_w2[(base + k + 1) * A_ + a];
            }
            s_part[tid] = q0 + q1;
        }
        __syncthreads();
        if (tid < 64) {
            float nm = r_mb2;
#pragma unroll
            for (int g = 0; g < 8; g++) nm += s_part[g * 64 + tid];
            float nv = (ops[b * L_ + t] == 0) ? nm : s_in[tid];
            s_in[tid] = nv;
            g_meta[(b * L_ + t) * A_ + tid] = nv;
        }
        __syncthreads();
    }
}

// ---------------- 3: proj (tinsum fused) --------------------------------------
__global__ void __launch_bounds__(256) k_proj(const float* __restrict__ cOut,
                                              const float* __restrict__ cIn) {
    int b = blockIdx.y;
    int tid = threadIdx.x;
    int w = tid >> 5, lane = tid & 31;
    __shared__ float s_arg[768];
    __shared__ float s_p[8][16];
    __shared__ float s_tin[64];
    if (tid < 64) s_tin[tid] = 0.f;
    for (int i = tid; i < 768; i += 256) s_arg[i] = g_arg[b * 768 + i];
    __syncthreads();
    int n = blockIdx.x * 8 + w;
    const float* rowO = (n < C_) ? cOut + (size_t)n * 64
                                 : g_objOut + (size_t)(b * O_ + n - C_) * 64;
    const float* rowI = (n < C_) ? cIn + (size_t)n * 64
                                 : g_objIn + (size_t)(b * O_ + n - C_) * 64;
    float x0 = rowO[lane], x1 = rowO[lane + 32];
    atomicAdd(&s_tin[lane], rowI[lane]);
    atomicAdd(&s_tin[lane + 32], rowI[lane + 32]);
#pragma unroll
    for (int s = 0; s < 12; s++) {
        float p = x0 * s_arg[s * 64 + lane] + x1 * s_arg[s * 64 + 32 + lane];
#pragma unroll
        for (int o = 16; o > 0; o >>= 1) p += __shfl_xor_sync(0xffffffffu, p, o);
        if (lane == 0) s_p[w][s] = p * (1.0f / 64.0f);
    }
    __syncwarp();
    if (lane < 16) {
        float v = (lane < 12) ? s_p[w][lane] : ((lane == 12) ? 1.0f : 0.0f);
        g_proj[(size_t)(b * N_ + n) * 16 + lane] = v;
        if (lane < 12) atomicAdd(&g_psum[b * 16 + lane], v);
    }
    __syncthreads();
    if (tid < 64) atomicAdd(&g_tInsum[b * 64 + tid], s_tin[tid]);
}

// ---------------- 4: k_D via mma.sync bf16-split --------------------------------
// grid (NSPLIT, L_, B_), 256 threads. Warp w owns h in [32w, 32w+32).
// smem (floats): s_A[64][257] relu tile | s_X[64][84] | s_u[256] | s_mt[64]
constexpr int SA_STR = 257, SX_STR = 84;
constexpr int OFF_SX = 64 * SA_STR;             // 16448
constexpr int OFF_SU = OFF_SX + 64 * SX_STR;    // 21824
constexpr int OFF_SMT = OFF_SU + 256;           // 22080
constexpr int KD_SMEM = (OFF_SMT + 64) * 4;     // 88576 bytes

__global__ void __launch_bounds__(256, 2) k_D(const int* __restrict__ ops,
                                              const float* __restrict__ cIn,
                                              const float* __restrict__ aw1,
                                              const float* __restrict__ ab1) {
    int t = blockIdx.y, b = blockIdx.z;
    if (ops[b * L_ + t] != 2) return;
    extern __shared__ float dyn[];
    float* s_A = dyn;
    float* s_X = dyn + OFF_SX;
    float* s_u = dyn + OFF_SU;
    float* s_mt = dyn + OFF_SMT;
    int tid = threadIdx.x;
    int wid = tid >> 5, lane = tid & 31;
    int gid = lane >> 2, tg = lane & 3;

    if (tid < 64) s_mt[tid] = g_meta[(b * L_ + t) * A_ + tid];
    __syncthreads();
    {   // u[h]
        float u0 = 0.f, u1 = 0.f, u2 = 0.f, u3 = 0.f;
#pragma unroll 4
        for (int a = 0; a < 64; a += 4) {
            u0 += s_mt[a] * __ldg(&aw1[(64 + a) * H_ + tid]);
            u1 += s_mt[a + 1] * __ldg(&aw1[(65 + a) * H_ + tid]);
            u2 += s_mt[a + 2] * __ldg(&aw1[(66 + a) * H_ + tid]);
            u3 += s_mt[a + 3] * __ldg(&aw1[(67 + a) * H_ + tid]);
        }
        s_u[tid] = ab1[tid] + ((u0 + u1) + (u2 + u3));
    }
    __syncthreads();
    float uh = s_u[tid];

    float acc[80];   // [m2][nt10][q4] -> m*40 + nt*4 + q
#pragma unroll
    for (int j = 0; j < 80; j++) acc[j] = 0.f;

    for (int tt = 0; tt < 6; tt++) {
        int tile = blockIdx.x * 6 + tt;
        int n0 = tile * 64;
        bool isC = (n0 < C_);
        if (tt) __syncthreads();   // prev tile fully consumed
        {   // stage relu(T1+u): column tid over 64 n-rows
            const float* t1 = (isC ? g_T1c + (size_t)n0 * H_
                                   : g_T1o + (size_t)(b * O_ + n0 - C_) * H_) + tid;
#pragma unroll 8
            for (int n = 0; n < 64; n++)
                s_A[n * SA_STR + tid] = fmaxf(t1[(size_t)n * H_] + uh, 0.f);
        }
        {   // stage X (f32)
            const float* tin = isC ? cIn + (size_t)n0 * 64
                                   : g_objIn + (size_t)(b * O_ + n0 - C_) * 64;
            const float* prj = g_proj + (size_t)(b * N_ + n0) * 16;
            for (int i = tid; i < 5120; i += 256) {
                int n = i / 80, c = i - n * 80;
                float v = (c < 64) ? tin[n * 64 + c] : prj[n * 16 + (c - 64)];
                s_X[n * SX_STR + c] = v;
            }
        }
        __syncthreads();

#pragma unroll
        for (int k = 0; k < 4; k++) {
            int k0 = k * 16;
            unsigned aH[8], aL[8];
#pragma unroll
            for (int m = 0; m < 2; m++) {
                int r0 = wid * 32 + m * 16 + gid;
                int r1 = r0 + 8;
                int c0 = k0 + tg * 2;
                float f00 = s_A[c0 * SA_STR + r0],  f01 = s_A[(c0 + 1) * SA_STR + r0];
                float f10 = s_A[c0 * SA_STR + r1],  f11 = s_A[(c0 + 1) * SA_STR + r1];
                float f20 = s_A[(c0 + 8) * SA_STR + r0], f21 = s_A[(c0 + 9) * SA_STR + r0];
                float f30 = s_A[(c0 + 8) * SA_STR + r1], f31 = s_A[(c0 + 9) * SA_STR + r1];
                aH[m * 4 + 0] = cvt_bf16x2(f01, f00);
                aH[m * 4 + 1] = cvt_bf16x2(f11, f10);
                aH[m * 4 + 2] = cvt_bf16x2(f21, f20);
                aH[m * 4 + 3] = cvt_bf16x2(f31, f30);
                aL[m * 4 + 0] = bf16_lo(aH[m * 4 + 0], f01, f00);
                aL[m * 4 + 1] = bf16_lo(aH[m * 4 + 1], f11, f10);
                aL[m * 4 + 2] = bf16_lo(aH[m * 4 + 2], f21, f20);
                aL[m * 4 + 3] = bf16_lo(aH[m * 4 + 3], f31, f30);
            }
#pragma unroll
            for (int nt = 0; nt < 10; nt++) {
                int cc = nt * 8 + gid;
                int nr = k0 + tg * 2;
                float g0 = s_X[nr * SX_STR + cc];
                float g1 = s_X[(nr + 1) * SX_STR + cc];
                float g2 = s_X[(nr + 8) * SX_STR + cc];
                float g3 = s_X[(nr + 9) * SX_STR + cc];
                unsigned bH[2], bL[2];
                bH[0] = cvt_bf16x2(g1, g0);
                bH[1] = cvt_bf16x2(g3, g2);
                bL[0] = bf16_lo(bH[0], g1, g0);
                bL[1] = bf16_lo(bH[1], g3, g2);
#pragma unroll
                for (int m = 0; m < 2; m++) {
                    float* d = acc + m * 40 + nt * 4;
                    mma_bf16(d, aH + m * 4, bH);
                    mma_bf16(d, aH + m * 4, bL);
                    mma_bf16(d, aL + m * 4, bH);
                }
            }
        }
    }

    // writeout: D[h][c] += acc
#pragma unroll
    for (int m = 0; m < 2; m++) {
        int h0 = wid * 32 + m * 16 + gid;
        float* dp0 = g_D + ((size_t)(b * L_ + t) * H_ + h0) * DCOLS;
        float* dp1 = g_D + ((size_t)(b * L_ + t) * H_ + h0 + 8) * DCOLS;
#pragma unroll
        for (int nt = 0; nt < 10; nt++) {
            int c0 = nt * 8 + tg * 2;
            const float* d = acc + m * 40 + nt * 4;
            asm volatile("red.global.add.v2.f32 [%0], {%1, %2};"
                         :: "l"(dp0 + c0), "f"(d[0]), "f"(d[1]) : "memory");
            asm volatile("red.global.add.v2.f32 [%0], {%1, %2};"
                         :: "l"(dp1 + c0), "f"(d[2]), "f"(d[3]) : "memory");
        }
    }
}

// ---------------- 5: k_E: E_t = W2^T @ D_t  (stored transposed [c][e']) --------
__global__ void __launch_bounds__(256) k_E(const int* __restrict__ ops,
                                           const float* __restrict__ w2) {
    int t = blockIdx.x, b = blockIdx.y;
    if (ops[b * L_ + t] != 2) return;
    int tid = threadIdx.x;
    int ep = tid & 63;
    int cq = tid >> 6;
    __shared__ __align__(16) float s_D[64 * 80];
    __shared__ __align__(16) float s_w2[64 * 64];
    unsigned long long acc[10];
#pragma unroll
    for (int j = 0; j < 10; j++) acc[j] = 0ULL;
    size_t dbase = (size_t)(b * L_ + t) * H_ * DCOLS;
    for (int ch = 0; ch < 4; ch++) {
        __syncthreads();
        {
            const float4* src = (const float4*)(g_D + dbase + ch * 64 * DCOLS);
            float4* dst = (float4*)s_D;
            for (int i = tid; i < 1280; i += 256) dst[i] = src[i];
            const float4* wsrc = (const float4*)(w2 + ch * 64 * 64);
            float4* wdst = (float4*)s_w2;
            for (int i = tid; i < 1024; i += 256) wdst[i] = wsrc[i];
        }
        __syncthreads();
        const unsigned long long* D2 = (const unsigned long long*)s_D;
#pragma unroll 8
        for (int hh = 0; hh < 64; hh++) {
            unsigned long long w2v = pack2(s_w2[hh * 64 + ep]);
            const unsigned long long* drow = D2 + hh * 40 + cq * 10;
#pragma unroll
            for (int j = 0; j < 10; j++) {
                asm("fma.rn.f32x2 %0, %1, %2, %0;" : "+l"(acc[j]) : "l"(w2v), "l"(drow[j]));
            }
        }
    }
    float* eb = g_E + (size_t)(b * L_ + t) * DCOLS * 64;
#pragma unroll
    for (int j = 0; j < 10; j++) {
        int c = cq * 20 + 2 * j;
        eb[c * 64 + ep] = lo2(acc[j]);
        eb[(c + 1) * 64 + ep] = hi2(acc[j]);
    }
}

// ---------------- 6: tiny serial recurrence: Msum, attsum ----------------------
__global__ void __launch_bounds__(1024) k_rec(const int* __restrict__ ops,
                                              const float* __restrict__ b2,
                                              const float* __restrict__ att_init) {
    __shared__ __align__(16) float s_Ms[4096];
    __shared__ __align__(16) float s_E[5120];
    __shared__ float s_meta[768], s_tmp[1024];
    __shared__ float s_as[64], s_ai[64], s_tis[64], s_b2[64], s_ps[12];
    __shared__ int s_op[12];
    int b = blockIdx.x, tid = threadIdx.x;
    for (int i = tid; i < 4096; i += 1024) s_Ms[i] = 0.f;
    if (tid < 768) s_meta[tid] = g_meta[b * 768 + tid];
    if (tid < 64) {
        s_ai[tid] = att_init[tid];
        s_as[tid] = (float)N_ * att_init[tid];
        s_tis[tid] = g_tInsum[b * 64 + tid];
        s_b2[tid] = b2[tid];
    }
    if (tid < 12) { s_op[tid] = ops[b * L_ + tid]; s_ps[tid] = g_psum[b * 16 + tid]; }
    __syncthreads();
    const float invN = 1.0f / (float)N_;
    int a = tid & 63, eg = tid >> 6;
    int e0 = eg * 4;
    for (int t = 0; t < L_; t++) {
        int op = s_op[t];
        if (op == 1) {
            if (tid < 64) s_as[tid] += s_ps[t] * s_meta[t * 64 + tid];
            __syncthreads();
        } else if (op == 2) {
            const float* esrc = g_E + (size_t)(b * L_ + t) * 5120;
            for (int i = tid; i < 5120; i += 1024) s_E[i] = esrc[i];
            __syncthreads();
            unsigned long long ai2 = pack2(s_ai[a]);
            unsigned long long acc2[2], bcc2[2];
            {
                ulonglong2 es = *(const ulonglong2*)(s_E + 76 * 64 + e0);
                acc2[0] = 0ULL; acc2[1] = 0ULL; bcc2[0] = 0ULL; bcc2[1] = 0ULL;
                asm("fma.rn.f32x2 %0, %1, %2, %0;" : "+l"(acc2[0]) : "l"(es.x), "l"(ai2));
                asm("fma.rn.f32x2 %0, %1, %2, %0;" : "+l"(acc2[1]) : "l"(es.y), "l"(ai2));
            }
            for (int s = 0; s < t; s++)
                if (s_op[s] == 1) {
                    unsigned long long mv = pack2(s_meta[s * 64 + a]);
                    ulonglong2 er = *(const ulonglong2*)(s_E + (64 + s) * 64 + e0);
                    asm("fma.rn.f32x2 %0, %1, %2, %0;" : "+l"(acc2[0]) : "l"(er.x), "l"(mv));
                    asm("fma.rn.f32x2 %0, %1, %2, %0;" : "+l"(acc2[1]) : "l"(er.y), "l"(mv));
                }
#pragma unroll 4
            for (int e = 0; e < 64; e += 2) {
                unsigned long long m0 = pack2(s_Ms[e * 64 + a]);
                ulonglong2 k0 = *(const ulonglong2*)(s_E + e * 64 + e0);
                asm("fma.rn.f32x2 %0, %1, %2, %0;" : "+l"(acc2[0]) : "l"(k0.x), "l"(m0));
                asm("fma.rn.f32x2 %0, %1, %2, %0;" : "+l"(acc2[1]) : "l"(k0.y), "l"(m0));
                unsigned long long m1 = pack2(s_Ms[(e + 1) * 64 + a]);
                ulonglong2 k1 = *(const ulonglong2*)(s_E + (e + 1) * 64 + e0);
                asm("fma.rn.f32x2 %0, %1, %2, %0;" : "+l"(bcc2[0]) : "l"(k1.x), "l"(m1));
                asm("fma.rn.f32x2 %0, %1, %2, %0;" : "+l"(bcc2[1]) : "l"(k1.y), "l"(m1));
            }
            float asv = s_as[a];
            float m[4] = {lo2(acc2[0]) + lo2(bcc2[0]), hi2(acc2[0]) + hi2(bcc2[0]),
                          lo2(acc2[1]) + lo2(bcc2[1]), hi2(acc2[1]) + hi2(bcc2[1])};
            float part = 0.f;
#pragma unroll
            for (int j = 0; j < 4; j++) {
                m[j] = (m[j] + s_b2[e0 + j] * asv) * invN;
                part += s_tis[e0 + j] * m[j];
            }
            s_tmp[eg * 64 + a] = part;
            __syncthreads();
#pragma unroll
            for (int j = 0; j < 4; j++) s_Ms[(e0 + j) * 64 + a] += m[j];
            if (tid < 64) {
                float d = 0.f;
#pragma unroll
                for (int g = 0; g < 16; g++) d += s_tmp[g * 64 + tid];
                s_as[tid] += d;
            }
            __syncthreads();
        }
    }
    for (int i = tid; i < 4096; i += 1024) g_Msum[b * 4096 + i] = s_Ms[i];
}

// ---------------- 7: final: att rows, ol, max (32 rows/block) ------------------
__global__ void __launch_bounds__(128) k_final(const int* __restrict__ ops,
                                               const float* __restrict__ cIn,
                                               const float* __restrict__ att_init) {
    int b = blockIdx.y;
    int ag = threadIdx.x;
    int ny = threadIdx.y;
    int tid = ny * 16 + ag;
    __shared__ float s_Ms[4096], s_meta[768], s_ai[64];
    __shared__ float s_ti[8][64], s_pr[8][16];
    __shared__ int s_opf[12];
    for (int i = tid; i < 4096; i += 128) s_Ms[i] = g_Msum[b * 4096 + i];
    for (int i = tid; i < 768; i += 128) s_meta[i] = g_meta[b * 768 + i];
    if (tid < 64) s_ai[tid] = att_init[tid];
    if (tid < 12) s_opf[tid] = ops[b * L_ + tid];
    int base = blockIdx.x * 32;
    for (int g4 = 0; g4 < 4; g4++) {
        int n0 = base + g4 * 8;
        __syncthreads();
        for (int i = tid; i < 512; i += 128) {
            int r = i >> 6, e = i & 63;
            int n = n0 + r;
            const float* row = (n < C_) ? cIn + (size_t)n * 64
                                        : g_objIn + (size_t)(b * O_ + n - C_) * 64;
            s_ti[r][e] = row[e];
        }
        {
            int r = tid >> 4, c = tid & 15;
            s_pr[r][c] = g_proj[(size_t)(b * N_ + n0 + r) * 16 + c];
        }
        __syncthreads();
        int n = n0 + ny;
        int a0 = ag * 4;
        float v0 = s_ai[a0], v1 = s_ai[a0 + 1], v2 = s_ai[a0 + 2], v3 = s_ai[a0 + 3];
#pragma unroll
        for (int s = 0; s < 12; s++)
            if (s_opf[s] == 1) {
                float pp = s_pr[ny][s];
                v0 += pp * s_meta[s * 64 + a0];
                v1 += pp * s_meta[s * 64 + a0 + 1];
                v2 += pp * s_meta[s * 64 + a0 + 2];
                v3 += pp * s_meta[s * 64 + a0 + 3];
            }
        const float4* Ms4 = (const float4*)s_Ms;
#pragma unroll
        for (int e = 0; e < 64; e++) {
            float ti = s_ti[ny][e];
            float4 m = Ms4[e * 16 + ag];
            v0 += ti * m.x; v1 += ti * m.y; v2 += ti * m.z; v3 += ti * m.w;
        }
        float sq = v0 * v0 + v1 * v1 + v2 * v2 + v3 * v3;
#pragma unroll
        for (int o = 8; o > 0; o >>= 1) sq += __shfl_xor_sync(0xffffffffu, sq, o);
        if (ag == 0) {
            float ol = sq * (1.0f / 64.0f);
            g_ol[b * N_ + n] = ol;
            atomicMax(&g_olmax[b], __float_as_int(ol));  // ol >= 0
        }
    }
}

// ---------------- 8: softmax ----------------------------------------------------
__global__ void __launch_bounds__(1024) k_soft(float* __restrict__ out) {
    int b = blockIdx.x;
    int tid = threadIdx.x;
    __shared__ float s_red[1024];
    float mx = __int_as_float(g_olmax[b]);
    float lsum = 0.f;
    for (int n = tid; n < N_; n += 1024) lsum += expf(g_ol[b * N_ + n] - mx);
    s_red[tid] = lsum;
    __syncthreads();
    for (int s = 512; s > 0; s >>= 1) {
        if (tid < s) s_red[tid] += s_red[tid + s];
        __syncthreads();
    }
    float lse = logf(s_red[0]) + mx;
    for (int n = tid; n < N_; n += 1024) out[b * N_ + n] = g_ol[b * N_ + n] - lse;
}

// ---------------- launch --------------------------------------------------------
extern "C" void kernel_launch(void* const* d_in, const int* in_sizes, int n_in,
                              void* d_out, int out_size) {
    const float* class_embIn   = (const float*)d_in[0];
    const float* class_embOut  = (const float*)d_in[1];
    const float* attr_embIn    = (const float*)d_in[2];
    const float* attr_embOut   = (const float*)d_in[3];
    const float* concept_embIn = (const float*)d_in[4];
    const float* concept_embOut= (const float*)d_in[5];
    const float* meta_init     = (const float*)d_in[6];
    const float* attention_init= (const float*)d_in[8];
    const float* axon_w1       = (const float*)d_in[9];
    const float* axon_b1       = (const float*)d_in[10];
    const float* axon_w2       = (const float*)d_in[11];
    const float* axon_b2       = (const float*)d_in[12];
    const float* meta_w1       = (const float*)d_in[13];
    const float* meta_b1       = (const float*)d_in[14];
    const float* meta_w2       = (const float*)d_in[15];
    const float* meta_b2       = (const float*)d_in[16];
    const int*   program_ops   = (const int*)d_in[17];
    const int*   program_args  = (const int*)d_in[18];
    const int*   gt_classes    = (const int*)d_in[19];
    const int*   gt_attributes = (const int*)d_in[20];
    float* out = (float*)d_out;

    cudaFuncSetAttribute(k_meta, cudaFuncAttributeMaxDynamicSharedMemorySize,
                         49152 * (int)sizeof(float));
    cudaFuncSetAttribute(k_D, cudaFuncAttributeMaxDynamicSharedMemorySize, KD_SMEM);

    k_pre<<<345, 256>>>(class_embIn, class_embOut, attr_embIn, attr_embOut,
                        gt_classes, gt_attributes, axon_w1, concept_embOut,
                        program_args);
    k_meta<<<B_, 512, 49152 * sizeof(float)>>>(meta_init, meta_w1, meta_b1,
                                               meta_w2, meta_b2, program_ops);
    k_proj<<<dim3(N_ / 8, B_), 256>>>(concept_embOut, concept_embIn);
    k_D<<<dim3(NSPLIT, L_, B_), 256, KD_SMEM>>>(program_ops, concept_embIn,
                                                axon_w1, axon_b1);
    k_E<<<dim3(L_, B_), 256>>>(program_ops, axon_w2);
    k_rec<<<B_, 1024>>>(program_ops, axon_b2, attention_init);
    k_final<<<dim3(N_ / 32, B_), dim3(16, 8)>>>(program_ops, concept_embIn,
                                                attention_init);
    k_soft<<<B_, 1024>>>(out);
}

// round 16
// speedup vs baseline: 1.8278x; 1.0948x over previous
#include <cuda_runtime.h>

// Problem constants
constexpr int B_ = 8, L_ = 12, C_ = 4096, O_ = 128, N_ = 4224;
constexpr int E_ = 64, A_ = 64, H_ = 256;
constexpr int DCOLS = 80;
constexpr int NTILES = N_ / 64;        // 66
constexpr int NSPLIT = 22;             // blocks per (b,t); 3 tiles each
constexpr int TPB = NTILES / NSPLIT;   // 3

// ---------------- scratch (device globals) ----------------------------------
__device__ __align__(16) float g_objIn[B_ * O_ * E_];
__device__ __align__(16) float g_objOut[B_ * O_ * E_];
__device__ __align__(16) float g_T1c[C_ * H_];
__device__ __align__(16) float g_T1o[B_ * O_ * H_];
__device__ __align__(16) float g_meta[B_ * L_ * A_];
__device__ __align__(16) float g_arg[B_ * L_ * E_];
__device__ __align__(16) float g_proj[B_ * N_ * 16];
__device__ __align__(16) float g_psum[B_ * 16];
__device__ __align__(16) float g_tInsum[B_ * E_];
__device__ __align__(16) float g_D[B_ * L_ * H_ * DCOLS];   // [bt][h][c]
__device__ __align__(16) float g_E[B_ * L_ * DCOLS * 64];   // [bt][c][e']
__device__ __align__(16) float g_Msum[B_ * E_ * A_];
__device__ __align__(16) float g_ol[B_ * N_];
__device__ int g_olmax[B_];
// Pre-packed bf16 hi/lo B tiles in mma fragment layout: [b][tile][p(32)][cc(80)]
__device__ __align__(16) unsigned g_Xhi[B_ * NTILES * 2560];
__device__ __align__(16) unsigned g_Xlo[B_ * NTILES * 2560];

__device__ __forceinline__ unsigned long long pack2(float v) {
    unsigned int b = __float_as_uint(v);
    return ((unsigned long long)b << 32) | b;
}
__device__ __forceinline__ float lo2(unsigned long long v) {
    return __uint_as_float((unsigned)(v & 0xffffffffULL));
}
__device__ __forceinline__ float hi2(unsigned long long v) {
    return __uint_as_float((unsigned)(v >> 32));
}
// pack two floats to bf16x2: f1 -> high half, f0 -> low half
__device__ __forceinline__ unsigned cvt_bf16x2(float f1, float f0) {
    unsigned r;
    asm("cvt.rn.satfinite.bf16x2.f32 %0, %1, %2;" : "=r"(r) : "f"(f1), "f"(f0));
    return r;
}
__device__ __forceinline__ unsigned bf16_lo(unsigned hi01, float f1, float f0) {
    float f0r = __uint_as_float(hi01 << 16);
    float f1r = __uint_as_float(hi01 & 0xffff0000u);
    return cvt_bf16x2(f1 - f1r, f0 - f0r);
}
__device__ __forceinline__ void mma_bf16(float* d, const unsigned* a, const unsigned* b) {
    asm volatile(
        "mma.sync.aligned.m16n8k16.row.col.f32.bf16.bf16.f32 "
        "{%0,%1,%2,%3}, {%4,%5,%6,%7}, {%8,%9}, {%0,%1,%2,%3};"
        : "+f"(d[0]), "+f"(d[1]), "+f"(d[2]), "+f"(d[3])
        : "r"(a[0]), "r"(a[1]), "r"(a[2]), "r"(a[3]), "r"(b[0]), "r"(b[1]));
}

// ---------------- 1: fused precompute: T1c | objT1o | zero | arg gather -------
__global__ void __launch_bounds__(256) k_pre(
    const float* __restrict__ clsIn, const float* __restrict__ clsOut,
    const float* __restrict__ atIn, const float* __restrict__ atOut,
    const int* __restrict__ gt_cls, const int* __restrict__ gt_attr,
    const float* __restrict__ w1, const float* __restrict__ cOut,
    const int* __restrict__ args) {
    int bx = blockIdx.x;
    int tid = threadIdx.x;
    __shared__ float s_emb[1024];
    __shared__ float s_w[4096];

    if (bx < 256) {
        int n0 = bx * 16;
        for (int i = tid; i < 1024; i += 256) s_emb[i] = cOut[n0 * E_ + i];
        float acc[16];
#pragma unroll
        for (int r = 0; r < 16; r++) acc[r] = 0.f;
        for (int ch = 0; ch < 4; ch++) {
            __syncthreads();
            {
                const float4* src = (const float4*)(w1 + ch * 16 * H_);
                float4* dst = (float4*)s_w;
                for (int i = tid; i < 1024; i += 256) dst[i] = src[i];
            }
            __syncthreads();
#pragma unroll
            for (int e = 0; e < 16; e++) {
                float w = s_w[e * H_ + tid];
                int ge = ch * 16 + e;
#pragma unroll
                for (int r = 0; r < 16; r++) acc[r] += s_emb[r * 64 + ge] * w;
            }
        }
#pragma unroll
        for (int r = 0; r < 16; r++) g_T1c[(n0 + r) * H_ + tid] = acc[r];
    } else if (bx < 320) {
        int idx = bx - 256;
        int b = idx >> 3;
        int o0 = (idx & 7) * 16;
        for (int i = tid; i < 1024; i += 256) {
            int r = i >> 6, e = i & 63;
            int o = o0 + r;
            int cls = gt_cls[b * O_ + o];
            float vi = clsIn[cls * E_ + e];
            float vo = clsOut[cls * E_ + e];
#pragma unroll
            for (int k = 0; k < 8; k++) {
                int at = gt_attr[(b * O_ + o) * 8 + k];
                vi += atIn[at * E_ + e];
                vo += atOut[at * E_ + e];
            }
            g_objIn[(b * O_ + o) * E_ + e] = vi;
            g_objOut[(b * O_ + o) * E_ + e] = vo;
            s_emb[i] = vo;
        }
        float acc[16];
#pragma unroll
        for (int r = 0; r < 16; r++) acc[r] = 0.f;
        for (int ch = 0; ch < 4; ch++) {
            __syncthreads();
            {
                const float4* src = (const float4*)(w1 + ch * 16 * H_);
                float4* dst = (float4*)s_w;
                for (int i = tid; i < 1024; i += 256) dst[i] = src[i];
            }
            __syncthreads();
#pragma unroll
            for (int e = 0; e < 16; e++) {
                float w = s_w[e * H_ + tid];
                int ge = ch * 16 + e;
#pragma unroll
                for (int r = 0; r < 16; r++) acc[r] += s_emb[r * 64 + ge] * w;
            }
        }
#pragma unroll
        for (int r = 0; r < 16; r++) g_T1o[(b * O_ + o0 + r) * H_ + tid] = acc[r];
    } else if (bx < 344) {
        int i = (bx - 320) * 256 + tid;   // 0..6143
        float4 z = make_float4(0.f, 0.f, 0.f, 0.f);
        float4* d4 = (float4*)g_D;
#pragma unroll
        for (int j = 0; j < 80; j++) d4[j * 6144 + i] = z;
        if (bx == 320) {
            if (tid < 128) g_psum[tid] = 0.f;
            g_tInsum[tid] = 0.f;
            g_tInsum[256 + tid] = 0.f;
            if (tid < 8) g_olmax[tid] = 0;
        }
    } else {
        for (int i = tid; i < B_ * L_ * E_; i += 256) {
            int bt = i >> 6, e = i & 63;
            g_arg[i] = cOut[args[bt] * E_ + e];
        }
    }
}

// ---------------- 2: meta recurrence (512 threads, split-K) -------------------
__global__ void __launch_bounds__(512) k_meta(
    const float* __restrict__ meta_init,
    const float* __restrict__ mw1, const float* __restrict__ mb1,
    const float* __restrict__ mw2, const float* __restrict__ mb2,
    const int* __restrict__ ops) {
    extern __shared__ float dsm[];
    float* s_w1 = dsm;
    float* s_w2 = dsm + 32768;
    __shared__ float s_in[128];
    __shared__ float s_h[256], s_pre[512], s_part[512];
    int b = blockIdx.x;
    int tid = threadIdx.x;
    {
        const float4* w1_4 = (const float4*)mw1;
        float4* d1 = (float4*)s_w1;
        for (int i = tid; i < 8192; i += 512) d1[i] = w1_4[i];
        const float4* w2_4 = (const float4*)mw2;
        float4* d2 = (float4*)s_w2;
        for (int i = tid; i < 4096; i += 512) d2[i] = w2_4[i];
    }
    float r_mb1 = (tid < 256) ? mb1[tid] : 0.f;
    float r_mb2 = (tid < 64) ? mb2[tid] : 0.f;
    if (tid < 64) s_in[tid] = meta_init[tid];
    __syncthreads();
    int h = tid & 255, half = tid >> 8;
    int a = tid & 63, pq = tid >> 6;
    for (int t = 0; t < L_; t++) {
        if (tid < 64) s_in[64 + tid] = g_arg[(b * L_ + t) * E_ + tid];
        __syncthreads();
        {
            int base = half * 64;
            float p0 = 0.f, p1 = 0.f, p2 = 0.f, p3 = 0.f;
#pragma unroll
            for (int k = 0; k < 64; k += 4) {
                p0 += s_in[base + k] * s_w1[(base + k) * H_ + h];
                p1 += s_in[base + k + 1] * s_w1[(base + k + 1) * H_ + h];
                p2 += s_in[base + k + 2] * s_w1[(base + k + 2) * H_ + h];
                p3 += s_in[base + k + 3] * s_w1[(base + k + 3) * H_ + h];
            }
            s_pre[tid] = (p0 + p1) + (p2 + p3);
        }
        __syncthreads();
        if (tid < 256) s_h[tid] = fmaxf(r_mb1 + s_pre[tid] + s_pre[256 + tid], 0.f);
        __syncthreads();
        {
            int base = pq * 32;
            float q0 = 0.f, q1 = 0.f;
#pragma unroll
            for (int k = 0; k < 32; k += 2) {
                q0 += s_h[base + k] * s_w2[(base + k) * A_ + a];
                q1 += s_h[base + k + 1] * s_w2[(base + k + 1) * A_ + a];
            }
            s_part[tid] = q0 + q1;
        }
        __syncthreads();
        if (tid < 64) {
            float nm = r_mb2;
#pragma unroll
            for (int g = 0; g < 8; g++) nm += s_part[g * 64 + tid];
            float nv = (ops[b * L_ + t] == 0) ? nm : s_in[tid];
            s_in[tid] = nv;
            g_meta[(b * L_ + t) * A_ + tid] = nv;
        }
        __syncthreads();
    }
}

// ---------------- 3: proj (tinsum fused) --------------------------------------
__global__ void __launch_bounds__(256) k_proj(const float* __restrict__ cOut,
                                              const float* __restrict__ cIn) {
    int b = blockIdx.y;
    int tid = threadIdx.x;
    int w = tid >> 5, lane = tid & 31;
    __shared__ float s_arg[768];
    __shared__ float s_p[8][16];
    __shared__ float s_tin[64];
    if (tid < 64) s_tin[tid] = 0.f;
    for (int i = tid; i < 768; i += 256) s_arg[i] = g_arg[b * 768 + i];
    __syncthreads();
    int n = blockIdx.x * 8 + w;
    const float* rowO = (n < C_) ? cOut + (size_t)n * 64
                                 : g_objOut + (size_t)(b * O_ + n - C_) * 64;
    const float* rowI = (n < C_) ? cIn + (size_t)n * 64
                                 : g_objIn + (size_t)(b * O_ + n - C_) * 64;
    float x0 = rowO[lane], x1 = rowO[lane + 32];
    atomicAdd(&s_tin[lane], rowI[lane]);
    atomicAdd(&s_tin[lane + 32], rowI[lane + 32]);
#pragma unroll
    for (int s = 0; s < 12; s++) {
        float p = x0 * s_arg[s * 64 + lane] + x1 * s_arg[s * 64 + 32 + lane];
#pragma unroll
        for (int o = 16; o > 0; o >>= 1) p += __shfl_xor_sync(0xffffffffu, p, o);
        if (lane == 0) s_p[w][s] = p * (1.0f / 64.0f);
    }
    __syncwarp();
    if (lane < 16) {
        float v = (lane < 12) ? s_p[w][lane] : ((lane == 12) ? 1.0f : 0.0f);
        g_proj[(size_t)(b * N_ + n) * 16 + lane] = v;
        if (lane < 12) atomicAdd(&g_psum[b * 16 + lane], v);
    }
    __syncthreads();
    if (tid < 64) atomicAdd(&g_tInsum[b * 64 + tid], s_tin[tid]);
}

// ---------------- 3.5: k_Xcvt: pre-pack bf16 hi/lo B fragments ------------------
// layout per (b,tile): out[p*80 + cc] = bf16x2( X[2p+1][cc], X[2p][cc] )
__global__ void __launch_bounds__(256) k_Xcvt(const float* __restrict__ cIn) {
    int tile = blockIdx.x, b = blockIdx.y;
    int n0 = tile * 64;
    bool isC = (n0 < C_);
    const float* tin = isC ? cIn + (size_t)n0 * 64
                           : g_objIn + (size_t)(b * O_ + n0 - C_) * 64;
    const float* prj = g_proj + (size_t)(b * N_ + n0) * 16;
    unsigned* oh = g_Xhi + (size_t)(b * NTILES + tile) * 2560;
    unsigned* ol = g_Xlo + (size_t)(b * NTILES + tile) * 2560;
    for (int i = threadIdx.x; i < 2560; i += 256) {
        int p = i / 80, cc = i - p * 80;
        int n = 2 * p;
        float f0, f1;
        if (cc < 64) {
            f0 = tin[n * 64 + cc];
            f1 = tin[(n + 1) * 64 + cc];
        } else {
            f0 = prj[n * 16 + (cc - 64)];
            f1 = prj[(n + 1) * 16 + (cc - 64)];
        }
        unsigned hi = cvt_bf16x2(f1, f0);
        oh[i] = hi;
        ol[i] = bf16_lo(hi, f1, f0);
    }
}

// ---------------- 4: k_D via mma.sync bf16-split (pre-packed fragments) --------
// smem (u32): Ahi[32p][264] | Alo | Bhi[32p][88] | Blo | u(256 f32) | mt(64 f32)
constexpr int AP = 264, BP = 88;
constexpr int OFF_ALO = 32 * AP;             // 8448
constexpr int OFF_BHI = 2 * 32 * AP;         // 16896
constexpr int OFF_BLO = OFF_BHI + 32 * BP;   // 19712
constexpr int OFF_SU = OFF_BLO + 32 * BP;    // 22528
constexpr int OFF_SMT = OFF_SU + 256;        // 22784
constexpr int KD_SMEM = (OFF_SMT + 64) * 4;  // 91392 bytes

__global__ void __launch_bounds__(256, 2) k_D(const int* __restrict__ ops,
                                              const float* __restrict__ aw1,
                                              const float* __restrict__ ab1) {
    int t = blockIdx.y, b = blockIdx.z;
    if (ops[b * L_ + t] != 2) return;
    extern __shared__ unsigned dynu[];
    unsigned* s_Ahi = dynu;
    unsigned* s_Alo = dynu + OFF_ALO;
    unsigned* s_Bhi = dynu + OFF_BHI;
    unsigned* s_Blo = dynu + OFF_BLO;
    float* s_u = (float*)(dynu + OFF_SU);
    float* s_mt = (float*)(dynu + OFF_SMT);
    int tid = threadIdx.x;
    int wid = tid >> 5, lane = tid & 31;
    int gid = lane >> 2, tg = lane & 3;

    if (tid < 64) s_mt[tid] = g_meta[(b * L_ + t) * A_ + tid];
    __syncthreads();
    {   // u[h]
        float u0 = 0.f, u1 = 0.f, u2 = 0.f, u3 = 0.f;
#pragma unroll 4
        for (int a = 0; a < 64; a += 4) {
            u0 += s_mt[a] * __ldg(&aw1[(64 + a) * H_ + tid]);
            u1 += s_mt[a + 1] * __ldg(&aw1[(65 + a) * H_ + tid]);
            u2 += s_mt[a + 2] * __ldg(&aw1[(66 + a) * H_ + tid]);
            u3 += s_mt[a + 3] * __ldg(&aw1[(67 + a) * H_ + tid]);
        }
        s_u[tid] = ab1[tid] + ((u0 + u1) + (u2 + u3));
    }
    __syncthreads();
    float uh = s_u[tid];

    float acc[80];   // [m2][nt10][q4]
#pragma unroll
    for (int j = 0; j < 80; j++) acc[j] = 0.f;

    for (int tt = 0; tt < TPB; tt++) {
        int tile = blockIdx.x * TPB + tt;
        int n0 = tile * 64;
        bool isC = (n0 < C_);
        if (tt) __syncthreads();
        {   // convert A: thread owns h = tid; pack along n into [p][h]
            const float* t1 = (isC ? g_T1c + (size_t)n0 * H_
                                   : g_T1o + (size_t)(b * O_ + n0 - C_) * H_) + tid;
#pragma unroll 4
            for (int p = 0; p < 32; p++) {
                float v0 = fmaxf(t1[(2 * p) * H_] + uh, 0.f);
                float v1 = fmaxf(t1[(2 * p + 1) * H_] + uh, 0.f);
                unsigned hi = cvt_bf16x2(v1, v0);
                s_Ahi[p * AP + tid] = hi;
                s_Alo[p * AP + tid] = bf16_lo(hi, v1, v0);
            }
        }
        {   // copy pre-packed B
            const unsigned* xh = g_Xhi + (size_t)(b * NTILES + tile) * 2560;
            const unsigned* xl = g_Xlo + (size_t)(b * NTILES + tile) * 2560;
            for (int i = tid; i < 2560; i += 256) {
                int p = i / 80, cc = i - p * 80;
                s_Bhi[p * BP + cc] = xh[i];
                s_Blo[p * BP + cc] = xl[i];
            }
        }
        __syncthreads();

#pragma unroll
        for (int k = 0; k < 4; k++) {
            int p0 = k * 8 + tg;
            unsigned aH[8], aL[8];
#pragma unroll
            for (int m = 0; m < 2; m++) {
                int r0 = wid * 32 + m * 16 + gid;
                aH[m * 4 + 0] = s_Ahi[p0 * AP + r0];
                aH[m * 4 + 1] = s_Ahi[p0 * AP + r0 + 8];
                aH[m * 4 + 2] = s_Ahi[(p0 + 4) * AP + r0];
                aH[m * 4 + 3] = s_Ahi[(p0 + 4) * AP + r0 + 8];
                aL[m * 4 + 0] = s_Alo[p0 * AP + r0];
                aL[m * 4 + 1] = s_Alo[p0 * AP + r0 + 8];
                aL[m * 4 + 2] = s_Alo[(p0 + 4) * AP + r0];
                aL[m * 4 + 3] = s_Alo[(p0 + 4) * AP + r0 + 8];
            }
#pragma unroll
            for (int nt = 0; nt < 10; nt++) {
                int cc = nt * 8 + gid;
                unsigned bH[2] = {s_Bhi[p0 * BP + cc], s_Bhi[(p0 + 4) * BP + cc]};
                unsigned bL[2] = {s_Blo[p0 * BP + cc], s_Blo[(p0 + 4) * BP + cc]};
#pragma unroll
                for (int m = 0; m < 2; m++) {
                    float* d = acc + m * 40 + nt * 4;
                    mma_bf16(d, aH + m * 4, bH);
                    mma_bf16(d, aH + m * 4, bL);
                    mma_bf16(d, aL + m * 4, bH);
                }
            }
        }
    }

    // writeout: D[h][c] += acc
#pragma unroll
    for (int m = 0; m < 2; m++) {
        int h0 = wid * 32 + m * 16 + gid;
        float* dp0 = g_D + ((size_t)(b * L_ + t) * H_ + h0) * DCOLS;
        float* dp1 = g_D + ((size_t)(b * L_ + t) * H_ + h0 + 8) * DCOLS;
#pragma unroll
        for (int nt = 0; nt < 10; nt++) {
            int c0 = nt * 8 + tg * 2;
            const float* d = acc + m * 40 + nt * 4;
            asm volatile("red.global.add.v2.f32 [%0], {%1, %2};"
                         :: "l"(dp0 + c0), "f"(d[0]), "f"(d[1]) : "memory");
            asm volatile("red.global.add.v2.f32 [%0], {%1, %2};"
                         :: "l"(dp1 + c0), "f"(d[2]), "f"(d[3]) : "memory");
        }
    }
}

// ---------------- 5: k_E: E_t = W2^T @ D_t  (stored transposed [c][e']) --------
__global__ void __launch_bounds__(256) k_E(const int* __restrict__ ops,
                                           const float* __restrict__ w2) {
    int t = blockIdx.x, b = blockIdx.y;
    if (ops[b * L_ + t] != 2) return;
    int tid = threadIdx.x;
    int ep = tid & 63;
    int cq = tid >> 6;
    __shared__ __align__(16) float s_D[64 * 80];
    __shared__ __align__(16) float s_w2[64 * 64];
    unsigned long long acc[10];
#pragma unroll
    for (int j = 0; j < 10; j++) acc[j] = 0ULL;
    size_t dbase = (size_t)(b * L_ + t) * H_ * DCOLS;
    for (int ch = 0; ch < 4; ch++) {
        __syncthreads();
        {
            const float4* src = (const float4*)(g_D + dbase + ch * 64 * DCOLS);
            float4* dst = (float4*)s_D;
            for (int i = tid; i < 1280; i += 256) dst[i] = src[i];
            const float4* wsrc = (const float4*)(w2 + ch * 64 * 64);
            float4* wdst = (float4*)s_w2;
            for (int i = tid; i < 1024; i += 256) wdst[i] = wsrc[i];
        }
        __syncthreads();
        const unsigned long long* D2 = (const unsigned long long*)s_D;
#pragma unroll 8
        for (int hh = 0; hh < 64; hh++) {
            unsigned long long w2v = pack2(s_w2[hh * 64 + ep]);
            const unsigned long long* drow = D2 + hh * 40 + cq * 10;
#pragma unroll
            for (int j = 0; j < 10; j++) {
                asm("fma.rn.f32x2 %0, %1, %2, %0;" : "+l"(acc[j]) : "l"(w2v), "l"(drow[j]));
            }
        }
    }
    float* eb = g_E + (size_t)(b * L_ + t) * DCOLS * 64;
#pragma unroll
    for (int j = 0; j < 10; j++) {
        int c = cq * 20 + 2 * j;
        eb[c * 64 + ep] = lo2(acc[j]);
        eb[(c + 1) * 64 + ep] = hi2(acc[j]);
    }
}

// ---------------- 6: tiny serial recurrence: Msum, attsum ----------------------
__global__ void __launch_bounds__(1024) k_rec(const int* __restrict__ ops,
                                              const float* __restrict__ b2,
                                              const float* __restrict__ att_init) {
    __shared__ __align__(16) float s_Ms[4096];
    __shared__ __align__(16) float s_E[5120];
    __shared__ float s_meta[768], s_tmp[1024];
    __shared__ float s_as[64], s_ai[64], s_tis[64], s_b2[64], s_ps[12];
    __shared__ int s_op[12];
    int b = blockIdx.x, tid = threadIdx.x;
    for (int i = tid; i < 4096; i += 1024) s_Ms[i] = 0.f;
    if (tid < 768) s_meta[tid] = g_meta[b * 768 + tid];
    if (tid < 64) {
        s_ai[tid] = att_init[tid];
        s_as[tid] = (float)N_ * att_init[tid];
        s_tis[tid] = g_tInsum[b * 64 + tid];
        s_b2[tid] = b2[tid];
    }
    if (tid < 12) { s_op[tid] = ops[b * L_ + tid]; s_ps[tid] = g_psum[b * 16 + tid]; }
    __syncthreads();
    const float invN = 1.0f / (float)N_;
    int a = tid & 63, eg = tid >> 6;
    int e0 = eg * 4;
    for (int t = 0; t < L_; t++) {
        int op = s_op[t];
        if (op == 1) {
            if (tid < 64) s_as[tid] += s_ps[t] * s_meta[t * 64 + tid];
            __syncthreads();
        } else if (op == 2) {
            const float* esrc = g_E + (size_t)(b * L_ + t) * 5120;
            for (int i = tid; i < 5120; i += 1024) s_E[i] = esrc[i];
            __syncthreads();
            unsigned long long ai2 = pack2(s_ai[a]);
            unsigned long long acc2[2], bcc2[2];
            {
                ulonglong2 es = *(const ulonglong2*)(s_E + 76 * 64 + e0);
                acc2[0] = 0ULL; acc2[1] = 0ULL; bcc2[0] = 0ULL; bcc2[1] = 0ULL;
                asm("fma.rn.f32x2 %0, %1, %2, %0;" : "+l"(acc2[0]) : "l"(es.x), "l"(ai2));
                asm("fma.rn.f32x2 %0, %1, %2, %0;" : "+l"(acc2[1]) : "l"(es.y), "l"(ai2));
            }
            for (int s = 0; s < t; s++)
                if (s_op[s] == 1) {
                    unsigned long long mv = pack2(s_meta[s * 64 + a]);
                    ulonglong2 er = *(const ulonglong2*)(s_E + (64 + s) * 64 + e0);
                    asm("fma.rn.f32x2 %0, %1, %2, %0;" : "+l"(acc2[0]) : "l"(er.x), "l"(mv));
                    asm("fma.rn.f32x2 %0, %1, %2, %0;" : "+l"(acc2[1]) : "l"(er.y), "l"(mv));
                }
#pragma unroll 4
            for (int e = 0; e < 64; e += 2) {
                unsigned long long m0 = pack2(s_Ms[e * 64 + a]);
                ulonglong2 k0 = *(const ulonglong2*)(s_E + e * 64 + e0);
                asm("fma.rn.f32x2 %0, %1, %2, %0;" : "+l"(acc2[0]) : "l"(k0.x), "l"(m0));
                asm("fma.rn.f32x2 %0, %1, %2, %0;" : "+l"(acc2[1]) : "l"(k0.y), "l"(m0));
                unsigned long long m1 = pack2(s_Ms[(e + 1) * 64 + a]);
                ulonglong2 k1 = *(const ulonglong2*)(s_E + (e + 1) * 64 + e0);
                asm("fma.rn.f32x2 %0, %1, %2, %0;" : "+l"(bcc2[0]) : "l"(k1.x), "l"(m1));
                asm("fma.rn.f32x2 %0, %1, %2, %0;" : "+l"(bcc2[1]) : "l"(k1.y), "l"(m1));
            }
            float asv = s_as[a];
            float m[4] = {lo2(acc2[0]) + lo2(bcc2[0]), hi2(acc2[0]) + hi2(bcc2[0]),
                          lo2(acc2[1]) + lo2(bcc2[1]), hi2(acc2[1]) + hi2(bcc2[1])};
            float part = 0.f;
#pragma unroll
            for (int j = 0; j < 4; j++) {
                m[j] = (m[j] + s_b2[e0 + j] * asv) * invN;
                part += s_tis[e0 + j] * m[j];
            }
            s_tmp[eg * 64 + a] = part;
            __syncthreads();
#pragma unroll
            for (int j = 0; j < 4; j++) s_Ms[(e0 + j) * 64 + a] += m[j];
            if (tid < 64) {
                float d = 0.f;
#pragma unroll
                for (int g = 0; g < 16; g++) d += s_tmp[g * 64 + tid];
                s_as[tid] += d;
            }
            __syncthreads();
        }
    }
    for (int i = tid; i < 4096; i += 1024) g_Msum[b * 4096 + i] = s_Ms[i];
}

// ---------------- 7: final: att rows, ol, max (32 rows/block) ------------------
__global__ void __launch_bounds__(128) k_final(const int* __restrict__ ops,
                                               const float* __restrict__ cIn,
                                               const float* __restrict__ att_init) {
    int b = blockIdx.y;
    int ag = threadIdx.x;
    int ny = threadIdx.y;
    int tid = ny * 16 + ag;
    __shared__ float s_Ms[4096], s_meta[768], s_ai[64];
    __shared__ float s_ti[8][64], s_pr[8][16];
    __shared__ int s_opf[12];
    for (int i = tid; i < 4096; i += 128) s_Ms[i] = g_Msum[b * 4096 + i];
    for (int i = tid; i < 768; i += 128) s_meta[i] = g_meta[b * 768 + i];
    if (tid < 64) s_ai[tid] = att_init[tid];
    if (tid < 12) s_opf[tid] = ops[b * L_ + tid];
    int base = blockIdx.x * 32;
    for (int g4 = 0; g4 < 4; g4++) {
        int n0 = base + g4 * 8;
        __syncthreads();
        for (int i = tid; i < 512; i += 128) {
            int r = i >> 6, e = i & 63;
            int n = n0 + r;
            const float* row = (n < C_) ? cIn + (size_t)n * 64
                                        : g_objIn + (size_t)(b * O_ + n - C_) * 64;
            s_ti[r][e] = row[e];
        }
        {
            int r = tid >> 4, c = tid & 15;
            s_pr[r][c] = g_proj[(size_t)(b * N_ + n0 + r) * 16 + c];
        }
        __syncthreads();
        int n = n0 + ny;
        int a0 = ag * 4;
        float v0 = s_ai[a0], v1 = s_ai[a0 + 1], v2 = s_ai[a0 + 2], v3 = s_ai[a0 + 3];
#pragma unroll
        for (int s = 0; s < 12; s++)
            if (s_opf[s] == 1) {
                float pp = s_pr[ny][s];
                v0 += pp * s_meta[s * 64 + a0];
                v1 += pp * s_meta[s * 64 + a0 + 1];
                v2 += pp * s_meta[s * 64 + a0 + 2];
                v3 += pp * s_meta[s * 64 + a0 + 3];
            }
        const float4* Ms4 = (const float4*)s_Ms;
#pragma unroll
        for (int e = 0; e < 64; e++) {
            float ti = s_ti[ny][e];
            float4 m = Ms4[e * 16 + ag];
            v0 += ti * m.x; v1 += ti * m.y; v2 += ti * m.z; v3 += ti * m.w;
        }
        float sq = v0 * v0 + v1 * v1 + v2 * v2 + v3 * v3;
#pragma unroll
        for (int o = 8; o > 0; o >>= 1) sq += __shfl_xor_sync(0xffffffffu, sq, o);
        if (ag == 0) {
            float ol = sq * (1.0f / 64.0f);
            g_ol[b * N_ + n] = ol;
            atomicMax(&g_olmax[b], __float_as_int(ol));  // ol >= 0
        }
    }
}

// ---------------- 8: softmax ----------------------------------------------------
__global__ void __launch_bounds__(1024) k_soft(float* __restrict__ out) {
    int b = blockIdx.x;
    int tid = threadIdx.x;
    __shared__ float s_red[1024];
    float mx = __int_as_float(g_olmax[b]);
    float lsum = 0.f;
    for (int n = tid; n < N_; n += 1024) lsum += expf(g_ol[b * N_ + n] - mx);
    s_red[tid] = lsum;
    __syncthreads();
    for (int s = 512; s > 0; s >>= 1) {
        if (tid < s) s_red[tid] += s_red[tid + s];
        __syncthreads();
    }
    float lse = logf(s_red[0]) + mx;
    for (int n = tid; n < N_; n += 1024) out[b * N_ + n] = g_ol[b * N_ + n] - lse;
}

// ---------------- launch --------------------------------------------------------
extern "C" void kernel_launch(void* const* d_in, const int* in_sizes, int n_in,
                              void* d_out, int out_size) {
    const float* class_embIn   = (const float*)d_in[0];
    const float* class_embOut  = (const float*)d_in[1];
    const float* attr_embIn    = (const float*)d_in[2];
    const float* attr_embOut   = (const float*)d_in[3];
    const float* concept_embIn = (const float*)d_in[4];
    const float* concept_embOut= (const float*)d_in[5];
    const float* meta_init     = (const float*)d_in[6];
    const float* attention_init= (const float*)d_in[8];
    const float* axon_w1       = (const float*)d_in[9];
    const float* axon_b1       = (const float*)d_in[10];
    const float* axon_w2       = (const float*)d_in[11];
    const float* axon_b2       = (const float*)d_in[12];
    const float* meta_w1       = (const float*)d_in[13];
    const float* meta_b1       = (const float*)d_in[14];
    const float* meta_w2       = (const float*)d_in[15];
    const float* meta_b2       = (const float*)d_in[16];
    const int*   program_ops   = (const int*)d_in[17];
    const int*   program_args  = (const int*)d_in[18];
    const int*   gt_classes    = (const int*)d_in[19];
    const int*   gt_attributes = (const int*)d_in[20];
    float* out = (float*)d_out;

    cudaFuncSetAttribute(k_meta, cudaFuncAttributeMaxDynamicSharedMemorySize,
                         49152 * (int)sizeof(float));
    cudaFuncSetAttribute(k_D, cudaFuncAttributeMaxDynamicSharedMemorySize, KD_SMEM);

    k_pre<<<345, 256>>>(class_embIn, class_embOut, attr_embIn, attr_embOut,
                        gt_classes, gt_attributes, axon_w1, concept_embOut,
                        program_args);
    k_meta<<<B_, 512, 49152 * sizeof(float)>>>(meta_init, meta_w1, meta_b1,
                                               meta_w2, meta_b2, program_ops);
    k_proj<<<dim3(N_ / 8, B_), 256>>>(concept_embOut, concept_embIn);
    k_Xcvt<<<dim3(NTILES, B_), 256>>>(concept_embIn);
    k_D<<<dim3(NSPLIT, L_, B_), 256, KD_SMEM>>>(program_ops, axon_w1, axon_b1);
    k_E<<<dim3(L_, B_), 256>>>(program_ops, axon_w2);
    k_rec<<<B_, 1024>>>(program_ops, axon_b2, attention_init);
    k_final<<<dim3(N_ / 32, B_), dim3(16, 8)>>>(program_ops, concept_embIn,
                                                attention_init);
    k_soft<<<B_, 1024>>>(out);
}

// round 17
// speedup vs baseline: 1.9689x; 1.0772x over previous
#include <cuda_runtime.h>

// Problem constants
constexpr int B_ = 8, L_ = 12, C_ = 4096, O_ = 128, N_ = 4224;
constexpr int E_ = 64, A_ = 64, H_ = 256;
constexpr int DCOLS = 80;
constexpr int NTILES = N_ / 64;        // 66
constexpr int NSPLIT = 11;             // blocks per (b,t); 6 tiles each
constexpr int TPB = NTILES / NSPLIT;   // 6

// ---------------- scratch (device globals) ----------------------------------
__device__ __align__(16) float g_objIn[B_ * O_ * E_];
__device__ __align__(16) float g_objOut[B_ * O_ * E_];
__device__ __align__(16) float g_T1c[C_ * H_];
__device__ __align__(16) float g_T1o[B_ * O_ * H_];
__device__ __align__(16) float g_meta[B_ * L_ * A_];
__device__ __align__(16) float g_arg[B_ * L_ * E_];
__device__ __align__(16) float g_proj[B_ * N_ * 16];
__device__ __align__(16) float g_psum[B_ * 16];
__device__ __align__(16) float g_tInsum[B_ * E_];
__device__ __align__(16) float g_D[B_ * L_ * H_ * DCOLS];   // [bt][h][c]
__device__ __align__(16) float g_E[B_ * L_ * DCOLS * 64];   // [bt][c][e']
__device__ __align__(16) float g_Msum[B_ * E_ * A_];
__device__ __align__(16) float g_ol[B_ * N_];
__device__ int g_olmax[B_];
// Pre-packed bf16 hi/lo B tiles in mma fragment layout: [b][tile][p(32)][cc(80)]
__device__ __align__(16) unsigned g_Xhi[B_ * NTILES * 2560];
__device__ __align__(16) unsigned g_Xlo[B_ * NTILES * 2560];

__device__ __forceinline__ unsigned long long pack2(float v) {
    unsigned int b = __float_as_uint(v);
    return ((unsigned long long)b << 32) | b;
}
__device__ __forceinline__ float lo2(unsigned long long v) {
    return __uint_as_float((unsigned)(v & 0xffffffffULL));
}
__device__ __forceinline__ float hi2(unsigned long long v) {
    return __uint_as_float((unsigned)(v >> 32));
}
// pack two floats to bf16x2: f1 -> high half, f0 -> low half
__device__ __forceinline__ unsigned cvt_bf16x2(float f1, float f0) {
    unsigned r;
    asm("cvt.rn.satfinite.bf16x2.f32 %0, %1, %2;" : "=r"(r) : "f"(f1), "f"(f0));
    return r;
}
__device__ __forceinline__ unsigned bf16_lo(unsigned hi01, float f1, float f0) {
    float f0r = __uint_as_float(hi01 << 16);
    float f1r = __uint_as_float(hi01 & 0xffff0000u);
    return cvt_bf16x2(f1 - f1r, f0 - f0r);
}
__device__ __forceinline__ void mma_bf16(float* d, const unsigned* a, const unsigned* b) {
    asm volatile(
        "mma.sync.aligned.m16n8k16.row.col.f32.bf16.bf16.f32 "
        "{%0,%1,%2,%3}, {%4,%5,%6,%7}, {%8,%9}, {%0,%1,%2,%3};"
        : "+f"(d[0]), "+f"(d[1]), "+f"(d[2]), "+f"(d[3])
        : "r"(a[0]), "r"(a[1]), "r"(a[2]), "r"(a[3]), "r"(b[0]), "r"(b[1]));
}

// ---------------- 1: fused precompute: T1c | objT1o | zero | arg gather -------
__global__ void __launch_bounds__(256) k_pre(
    const float* __restrict__ clsIn, const float* __restrict__ clsOut,
    const float* __restrict__ atIn, const float* __restrict__ atOut,
    const int* __restrict__ gt_cls, const int* __restrict__ gt_attr,
    const float* __restrict__ w1, const float* __restrict__ cOut,
    const int* __restrict__ args) {
    int bx = blockIdx.x;
    int tid = threadIdx.x;
    __shared__ float s_emb[1024];
    __shared__ float s_w[4096];

    if (bx < 256) {
        int n0 = bx * 16;
        for (int i = tid; i < 1024; i += 256) s_emb[i] = cOut[n0 * E_ + i];
        float acc[16];
#pragma unroll
        for (int r = 0; r < 16; r++) acc[r] = 0.f;
        for (int ch = 0; ch < 4; ch++) {
            __syncthreads();
            {
                const float4* src = (const float4*)(w1 + ch * 16 * H_);
                float4* dst = (float4*)s_w;
                for (int i = tid; i < 1024; i += 256) dst[i] = src[i];
            }
            __syncthreads();
#pragma unroll
            for (int e = 0; e < 16; e++) {
                float w = s_w[e * H_ + tid];
                int ge = ch * 16 + e;
#pragma unroll
                for (int r = 0; r < 16; r++) acc[r] += s_emb[r * 64 + ge] * w;
            }
        }
#pragma unroll
        for (int r = 0; r < 16; r++) g_T1c[(n0 + r) * H_ + tid] = acc[r];
    } else if (bx < 320) {
        int idx = bx - 256;
        int b = idx >> 3;
        int o0 = (idx & 7) * 16;
        for (int i = tid; i < 1024; i += 256) {
            int r = i >> 6, e = i & 63;
            int o = o0 + r;
            int cls = gt_cls[b * O_ + o];
            float vi = clsIn[cls * E_ + e];
            float vo = clsOut[cls * E_ + e];
#pragma unroll
            for (int k = 0; k < 8; k++) {
                int at = gt_attr[(b * O_ + o) * 8 + k];
                vi += atIn[at * E_ + e];
                vo += atOut[at * E_ + e];
            }
            g_objIn[(b * O_ + o) * E_ + e] = vi;
            g_objOut[(b * O_ + o) * E_ + e] = vo;
            s_emb[i] = vo;
        }
        float acc[16];
#pragma unroll
        for (int r = 0; r < 16; r++) acc[r] = 0.f;
        for (int ch = 0; ch < 4; ch++) {
            __syncthreads();
            {
                const float4* src = (const float4*)(w1 + ch * 16 * H_);
                float4* dst = (float4*)s_w;
                for (int i = tid; i < 1024; i += 256) dst[i] = src[i];
            }
            __syncthreads();
#pragma unroll
            for (int e = 0; e < 16; e++) {
                float w = s_w[e * H_ + tid];
                int ge = ch * 16 + e;
#pragma unroll
                for (int r = 0; r < 16; r++) acc[r] += s_emb[r * 64 + ge] * w;
            }
        }
#pragma unroll
        for (int r = 0; r < 16; r++) g_T1o[(b * O_ + o0 + r) * H_ + tid] = acc[r];
    } else if (bx < 344) {
        int i = (bx - 320) * 256 + tid;   // 0..6143
        float4 z = make_float4(0.f, 0.f, 0.f, 0.f);
        float4* d4 = (float4*)g_D;
#pragma unroll
        for (int j = 0; j < 80; j++) d4[j * 6144 + i] = z;
        if (bx == 320) {
            if (tid < 128) g_psum[tid] = 0.f;
            g_tInsum[tid] = 0.f;
            g_tInsum[256 + tid] = 0.f;
            if (tid < 8) g_olmax[tid] = 0;
        }
    } else {
        for (int i = tid; i < B_ * L_ * E_; i += 256) {
            int bt = i >> 6, e = i & 63;
            g_arg[i] = cOut[args[bt] * E_ + e];
        }
    }
}

// ---------------- 2: meta recurrence (512 threads, split-K) -------------------
__global__ void __launch_bounds__(512) k_meta(
    const float* __restrict__ meta_init,
    const float* __restrict__ mw1, const float* __restrict__ mb1,
    const float* __restrict__ mw2, const float* __restrict__ mb2,
    const int* __restrict__ ops) {
    extern __shared__ float dsm[];
    float* s_w1 = dsm;
    float* s_w2 = dsm + 32768;
    __shared__ float s_in[128];
    __shared__ float s_h[256], s_pre[512], s_part[512];
    int b = blockIdx.x;
    int tid = threadIdx.x;
    {
        const float4* w1_4 = (const float4*)mw1;
        float4* d1 = (float4*)s_w1;
        for (int i = tid; i < 8192; i += 512) d1[i] = w1_4[i];
        const float4* w2_4 = (const float4*)mw2;
        float4* d2 = (float4*)s_w2;
        for (int i = tid; i < 4096; i += 512) d2[i] = w2_4[i];
    }
    float r_mb1 = (tid < 256) ? mb1[tid] : 0.f;
    float r_mb2 = (tid < 64) ? mb2[tid] : 0.f;
    if (tid < 64) s_in[tid] = meta_init[tid];
    __syncthreads();
    int h = tid & 255, half = tid >> 8;
    int a = tid & 63, pq = tid >> 6;
    for (int t = 0; t < L_; t++) {
        if (tid < 64) s_in[64 + tid] = g_arg[(b * L_ + t) * E_ + tid];
        __syncthreads();
        {
            int base = half * 64;
            float p0 = 0.f, p1 = 0.f, p2 = 0.f, p3 = 0.f;
#pragma unroll
            for (int k = 0; k < 64; k += 4) {
                p0 += s_in[base + k] * s_w1[(base + k) * H_ + h];
                p1 += s_in[base + k + 1] * s_w1[(base + k + 1) * H_ + h];
                p2 += s_in[base + k + 2] * s_w1[(base + k + 2) * H_ + h];
                p3 += s_in[base + k + 3] * s_w1[(base + k + 3) * H_ + h];
            }
            s_pre[tid] = (p0 + p1) + (p2 + p3);
        }
        __syncthreads();
        if (tid < 256) s_h[tid] = fmaxf(r_mb1 + s_pre[tid] + s_pre[256 + tid], 0.f);
        __syncthreads();
        {
            int base = pq * 32;
            float q0 = 0.f, q1 = 0.f;
#pragma unroll
            for (int k = 0; k < 32; k += 2) {
                q0 += s_h[base + k] * s_w2[(base + k) * A_ + a];
                q1 += s_h[base + k + 1] * s_w2[(base + k + 1) * A_ + a];
            }
            s_part[tid] = q0 + q1;
        }
        __syncthreads();
        if (tid < 64) {
            float nm = r_mb2;
#pragma unroll
            for (int g = 0; g < 8; g++) nm += s_part[g * 64 + tid];
            float nv = (ops[b * L_ + t] == 0) ? nm : s_in[tid];
            s_in[tid] = nv;
            g_meta[(b * L_ + t) * A_ + tid] = nv;
        }
        __syncthreads();
    }
}

// ---------------- 3: proj + tinsum + bf16 X pre-pack (fused, 64-row tiles) ----
__global__ void __launch_bounds__(256) k_proj(const float* __restrict__ cOut,
                                              const float* __restrict__ cIn) {
    int tile = blockIdx.x, b = blockIdx.y;
    int n0 = tile * 64;
    bool isC = (n0 < C_);
    int tid = threadIdx.x;
    int w = tid >> 5, lane = tid & 31;
    __shared__ float s_arg[768];
    __shared__ float s_pr[64 * 16];
    __shared__ float s_tin[64];
    __shared__ float s_ps[12];
    if (tid < 64) s_tin[tid] = 0.f;
    if (tid < 12) s_ps[tid] = 0.f;
    for (int i = tid; i < 768; i += 256) s_arg[i] = g_arg[b * 768 + i];
    __syncthreads();

    const float* tinb = isC ? cIn + (size_t)n0 * 64
                            : g_objIn + (size_t)(b * O_ + n0 - C_) * 64;
    const float* toutb = isC ? cOut + (size_t)n0 * 64
                             : g_objOut + (size_t)(b * O_ + n0 - C_) * 64;
    float t0 = 0.f, t1 = 0.f;
    float psloc[12];
#pragma unroll
    for (int s = 0; s < 12; s++) psloc[s] = 0.f;
    for (int r = 0; r < 8; r++) {
        int nl = w * 8 + r;
        const float* rowO = toutb + (size_t)nl * 64;
        const float* rowI = tinb + (size_t)nl * 64;
        float x0 = rowO[lane], x1 = rowO[lane + 32];
        t0 += rowI[lane];
        t1 += rowI[lane + 32];
#pragma unroll
        for (int s = 0; s < 12; s++) {
            float p = x0 * s_arg[s * 64 + lane] + x1 * s_arg[s * 64 + 32 + lane];
#pragma unroll
            for (int o = 16; o > 0; o >>= 1) p += __shfl_xor_sync(0xffffffffu, p, o);
            if (lane == 0) {
                float v = p * (1.0f / 64.0f);
                s_pr[nl * 16 + s] = v;
                psloc[s] += v;
            }
        }
        if (lane < 4) {
            s_pr[nl * 16 + 12 + lane] = (lane == 0) ? 1.0f : 0.0f;
        }
    }
    atomicAdd(&s_tin[lane], t0);
    atomicAdd(&s_tin[lane + 32], t1);
    if (lane == 0) {
#pragma unroll
        for (int s = 0; s < 12; s++) atomicAdd(&s_ps[s], psloc[s]);
    }
    __syncthreads();
    // write g_proj (coalesced), psum, tinsum
    {
        float4* gp = (float4*)(g_proj + (size_t)(b * N_ + n0) * 16);
        const float4* sp = (const float4*)s_pr;
        for (int i = tid; i < 256; i += 256) gp[i] = sp[i];
    }
    if (tid < 12) atomicAdd(&g_psum[b * 16 + tid], s_ps[tid]);
    if (tid >= 64 && tid < 128) atomicAdd(&g_tInsum[b * 64 + tid - 64], s_tin[tid - 64]);
    // ---- bf16 hi/lo pre-pack (B fragments) ----
    unsigned* oh = g_Xhi + (size_t)(b * NTILES + tile) * 2560;
    unsigned* ol = g_Xlo + (size_t)(b * NTILES + tile) * 2560;
    for (int i = tid; i < 2560; i += 256) {
        int p = i / 80, cc = i - p * 80;
        int n = 2 * p;
        float f0, f1;
        if (cc < 64) {
            f0 = tinb[n * 64 + cc];
            f1 = tinb[(n + 1) * 64 + cc];
        } else {
            f0 = s_pr[n * 16 + (cc - 64)];
            f1 = s_pr[(n + 1) * 16 + (cc - 64)];
        }
        unsigned hi = cvt_bf16x2(f1, f0);
        oh[i] = hi;
        ol[i] = bf16_lo(hi, f1, f0);
    }
}

// ---------------- 4: k_D via mma.sync bf16-split (pre-packed fragments) --------
// smem (u32): Ahi[32p][264] | Alo | Bhi[32p][88] | Blo | u(256 f32) | mt(64 f32)
constexpr int AP = 264, BP = 88;
constexpr int OFF_ALO = 32 * AP;             // 8448
constexpr int OFF_BHI = 2 * 32 * AP;         // 16896
constexpr int OFF_BLO = OFF_BHI + 32 * BP;   // 19712
constexpr int OFF_SU = OFF_BLO + 32 * BP;    // 22528
constexpr int OFF_SMT = OFF_SU + 256;        // 22784
constexpr int KD_SMEM = (OFF_SMT + 64) * 4;  // 91392 bytes

__global__ void __launch_bounds__(256, 2) k_D(const int* __restrict__ ops,
                                              const float* __restrict__ aw1,
                                              const float* __restrict__ ab1) {
    int t = blockIdx.y, b = blockIdx.z;
    if (ops[b * L_ + t] != 2) return;
    extern __shared__ unsigned dynu[];
    unsigned* s_Ahi = dynu;
    unsigned* s_Alo = dynu + OFF_ALO;
    unsigned* s_Bhi = dynu + OFF_BHI;
    unsigned* s_Blo = dynu + OFF_BLO;
    float* s_u = (float*)(dynu + OFF_SU);
    float* s_mt = (float*)(dynu + OFF_SMT);
    int tid = threadIdx.x;
    int wid = tid >> 5, lane = tid & 31;
    int gid = lane >> 2, tg = lane & 3;

    if (tid < 64) s_mt[tid] = g_meta[(b * L_ + t) * A_ + tid];
    __syncthreads();
    {   // u[h]
        float u0 = 0.f, u1 = 0.f, u2 = 0.f, u3 = 0.f;
#pragma unroll 4
        for (int a = 0; a < 64; a += 4) {
            u0 += s_mt[a] * __ldg(&aw1[(64 + a) * H_ + tid]);
            u1 += s_mt[a + 1] * __ldg(&aw1[(65 + a) * H_ + tid]);
            u2 += s_mt[a + 2] * __ldg(&aw1[(66 + a) * H_ + tid]);
            u3 += s_mt[a + 3] * __ldg(&aw1[(67 + a) * H_ + tid]);
        }
        s_u[tid] = ab1[tid] + ((u0 + u1) + (u2 + u3));
    }
    __syncthreads();
    float uh = s_u[tid];

    float acc[80];   // [m2][nt10][q4]
#pragma unroll
    for (int j = 0; j < 80; j++) acc[j] = 0.f;

    for (int tt = 0; tt < TPB; tt++) {
        int tile = blockIdx.x * TPB + tt;
        int n0 = tile * 64;
        bool isC = (n0 < C_);
        if (tt) __syncthreads();
        {   // convert A: thread owns h = tid; pack along n into [p][h]
            const float* t1 = (isC ? g_T1c + (size_t)n0 * H_
                                   : g_T1o + (size_t)(b * O_ + n0 - C_) * H_) + tid;
#pragma unroll 4
            for (int p = 0; p < 32; p++) {
                float v0 = fmaxf(t1[(2 * p) * H_] + uh, 0.f);
                float v1 = fmaxf(t1[(2 * p + 1) * H_] + uh, 0.f);
                unsigned hi = cvt_bf16x2(v1, v0);
                s_Ahi[p * AP + tid] = hi;
                s_Alo[p * AP + tid] = bf16_lo(hi, v1, v0);
            }
        }
        {   // copy pre-packed B
            const unsigned* xh = g_Xhi + (size_t)(b * NTILES + tile) * 2560;
            const unsigned* xl = g_Xlo + (size_t)(b * NTILES + tile) * 2560;
            for (int i = tid; i < 2560; i += 256) {
                int p = i / 80, cc = i - p * 80;
                s_Bhi[p * BP + cc] = xh[i];
                s_Blo[p * BP + cc] = xl[i];
            }
        }
        __syncthreads();

#pragma unroll
        for (int k = 0; k < 4; k++) {
            int p0 = k * 8 + tg;
            unsigned aH[8], aL[8];
#pragma unroll
            for (int m = 0; m < 2; m++) {
                int r0 = wid * 32 + m * 16 + gid;
                aH[m * 4 + 0] = s_Ahi[p0 * AP + r0];
                aH[m * 4 + 1] = s_Ahi[p0 * AP + r0 + 8];
                aH[m * 4 + 2] = s_Ahi[(p0 + 4) * AP + r0];
                aH[m * 4 + 3] = s_Ahi[(p0 + 4) * AP + r0 + 8];
                aL[m * 4 + 0] = s_Alo[p0 * AP + r0];
                aL[m * 4 + 1] = s_Alo[p0 * AP + r0 + 8];
                aL[m * 4 + 2] = s_Alo[(p0 + 4) * AP + r0];
                aL[m * 4 + 3] = s_Alo[(p0 + 4) * AP + r0 + 8];
            }
#pragma unroll
            for (int nt = 0; nt < 10; nt++) {
                int cc = nt * 8 + gid;
                unsigned bH[2] = {s_Bhi[p0 * BP + cc], s_Bhi[(p0 + 4) * BP + cc]};
                unsigned bL[2] = {s_Blo[p0 * BP + cc], s_Blo[(p0 + 4) * BP + cc]};
#pragma unroll
                for (int m = 0; m < 2; m++) {
                    float* d = acc + m * 40 + nt * 4;
                    mma_bf16(d, aH + m * 4, bH);
                    mma_bf16(d, aH + m * 4, bL);
                    mma_bf16(d, aL + m * 4, bH);
                }
            }
        }
    }

    // writeout: D[h][c] += acc
#pragma unroll
    for (int m = 0; m < 2; m++) {
        int h0 = wid * 32 + m * 16 + gid;
        float* dp0 = g_D + ((size_t)(b * L_ + t) * H_ + h0) * DCOLS;
        float* dp1 = g_D + ((size_t)(b * L_ + t) * H_ + h0 + 8) * DCOLS;
#pragma unroll
        for (int nt = 0; nt < 10; nt++) {
            int c0 = nt * 8 + tg * 2;
            const float* d = acc + m * 40 + nt * 4;
            asm volatile("red.global.add.v2.f32 [%0], {%1, %2};"
                         :: "l"(dp0 + c0), "f"(d[0]), "f"(d[1]) : "memory");
            asm volatile("red.global.add.v2.f32 [%0], {%1, %2};"
                         :: "l"(dp1 + c0), "f"(d[2]), "f"(d[3]) : "memory");
        }
    }
}

// ---------------- 5: k_E: E_t = W2^T @ D_t  (stored transposed [c][e']) --------
__global__ void __launch_bounds__(256) k_E(const int* __restrict__ ops,
                                           const float* __restrict__ w2) {
    int t = blockIdx.x, b = blockIdx.y;
    if (ops[b * L_ + t] != 2) return;
    int tid = threadIdx.x;
    int ep = tid & 63;
    int cq = tid >> 6;
    __shared__ __align__(16) float s_D[64 * 80];
    __shared__ __align__(16) float s_w2[64 * 64];
    unsigned long long acc[10];
#pragma unroll
    for (int j = 0; j < 10; j++) acc[j] = 0ULL;
    size_t dbase = (size_t)(b * L_ + t) * H_ * DCOLS;
    for (int ch = 0; ch < 4; ch++) {
        __syncthreads();
        {
            const float4* src = (const float4*)(g_D + dbase + ch * 64 * DCOLS);
            float4* dst = (float4*)s_D;
            for (int i = tid; i < 1280; i += 256) dst[i] = src[i];
            const float4* wsrc = (const float4*)(w2 + ch * 64 * 64);
            float4* wdst = (float4*)s_w2;
            for (int i = tid; i < 1024; i += 256) wdst[i] = wsrc[i];
        }
        __syncthreads();
        const unsigned long long* D2 = (const unsigned long long*)s_D;
#pragma unroll 8
        for (int hh = 0; hh < 64; hh++) {
            unsigned long long w2v = pack2(s_w2[hh * 64 + ep]);
            const unsigned long long* drow = D2 + hh * 40 + cq * 10;
#pragma unroll
            for (int j = 0; j < 10; j++) {
                asm("fma.rn.f32x2 %0, %1, %2, %0;" : "+l"(acc[j]) : "l"(w2v), "l"(drow[j]));
            }
        }
    }
    float* eb = g_E + (size_t)(b * L_ + t) * DCOLS * 64;
#pragma unroll
    for (int j = 0; j < 10; j++) {
        int c = cq * 20 + 2 * j;
        eb[c * 64 + ep] = lo2(acc[j]);
        eb[(c + 1) * 64 + ep] = hi2(acc[j]);
    }
}

// ---------------- 6: tiny serial recurrence: Msum, attsum ----------------------
__global__ void __launch_bounds__(1024) k_rec(const int* __restrict__ ops,
                                              const float* __restrict__ b2,
                                              const float* __restrict__ att_init) {
    __shared__ __align__(16) float s_Ms[4096];
    __shared__ __align__(16) float s_E[5120];
    __shared__ float s_meta[768], s_tmp[1024];
    __shared__ float s_as[64], s_ai[64], s_tis[64], s_b2[64], s_ps[12];
    __shared__ int s_op[12];
    int b = blockIdx.x, tid = threadIdx.x;
    for (int i = tid; i < 4096; i += 1024) s_Ms[i] = 0.f;
    if (tid < 768) s_meta[tid] = g_meta[b * 768 + tid];
    if (tid < 64) {
        s_ai[tid] = att_init[tid];
        s_as[tid] = (float)N_ * att_init[tid];
        s_tis[tid] = g_tInsum[b * 64 + tid];
        s_b2[tid] = b2[tid];
    }
    if (tid < 12) { s_op[tid] = ops[b * L_ + tid]; s_ps[tid] = g_psum[b * 16 + tid]; }
    __syncthreads();
    const float invN = 1.0f / (float)N_;
    int a = tid & 63, eg = tid >> 6;
    int e0 = eg * 4;
    for (int t = 0; t < L_; t++) {
        int op = s_op[t];
        if (op == 1) {
            if (tid < 64) s_as[tid] += s_ps[t] * s_meta[t * 64 + tid];
            __syncthreads();
        } else if (op == 2) {
            const float* esrc = g_E + (size_t)(b * L_ + t) * 5120;
            for (int i = tid; i < 5120; i += 1024) s_E[i] = esrc[i];
            __syncthreads();
            unsigned long long ai2 = pack2(s_ai[a]);
            unsigned long long acc2[2], bcc2[2];
            {
                ulonglong2 es = *(const ulonglong2*)(s_E + 76 * 64 + e0);
                acc2[0] = 0ULL; acc2[1] = 0ULL; bcc2[0] = 0ULL; bcc2[1] = 0ULL;
                asm("fma.rn.f32x2 %0, %1, %2, %0;" : "+l"(acc2[0]) : "l"(es.x), "l"(ai2));
                asm("fma.rn.f32x2 %0, %1, %2, %0;" : "+l"(acc2[1]) : "l"(es.y), "l"(ai2));
            }
            for (int s = 0; s < t; s++)
                if (s_op[s] == 1) {
                    unsigned long long mv = pack2(s_meta[s * 64 + a]);
                    ulonglong2 er = *(const ulonglong2*)(s_E + (64 + s) * 64 + e0);
                    asm("fma.rn.f32x2 %0, %1, %2, %0;" : "+l"(acc2[0]) : "l"(er.x), "l"(mv));
                    asm("fma.rn.f32x2 %0, %1, %2, %0;" : "+l"(acc2[1]) : "l"(er.y), "l"(mv));
                }
#pragma unroll 4
            for (int e = 0; e < 64; e += 2) {
                unsigned long long m0 = pack2(s_Ms[e * 64 + a]);
                ulonglong2 k0 = *(const ulonglong2*)(s_E + e * 64 + e0);
                asm("fma.rn.f32x2 %0, %1, %2, %0;" : "+l"(acc2[0]) : "l"(k0.x), "l"(m0));
                asm("fma.rn.f32x2 %0, %1, %2, %0;" : "+l"(acc2[1]) : "l"(k0.y), "l"(m0));
                unsigned long long m1 = pack2(s_Ms[(e + 1) * 64 + a]);
                ulonglong2 k1 = *(const ulonglong2*)(s_E + (e + 1) * 64 + e0);
                asm("fma.rn.f32x2 %0, %1, %2, %0;" : "+l"(bcc2[0]) : "l"(k1.x), "l"(m1));
                asm("fma.rn.f32x2 %0, %1, %2, %0;" : "+l"(bcc2[1]) : "l"(k1.y), "l"(m1));
            }
            float asv = s_as[a];
            float m[4] = {lo2(acc2[0]) + lo2(bcc2[0]), hi2(acc2[0]) + hi2(bcc2[0]),
                          lo2(acc2[1]) + lo2(bcc2[1]), hi2(acc2[1]) + hi2(bcc2[1])};
            float part = 0.f;
#pragma unroll
            for (int j = 0; j < 4; j++) {
                m[j] = (m[j] + s_b2[e0 + j] * asv) * invN;
                part += s_tis[e0 + j] * m[j];
            }
            s_tmp[eg * 64 + a] = part;
            __syncthreads();
#pragma unroll
            for (int j = 0; j < 4; j++) s_Ms[(e0 + j) * 64 + a] += m[j];
            if (tid < 64) {
                float d = 0.f;
#pragma unroll
                for (int g = 0; g < 16; g++) d += s_tmp[g * 64 + tid];
                s_as[tid] += d;
            }
            __syncthreads();
        }
    }
    for (int i = tid; i < 4096; i += 1024) g_Msum[b * 4096 + i] = s_Ms[i];
}

// ---------------- 7: final: att rows, ol, max (32 rows/block) ------------------
__global__ void __launch_bounds__(128) k_final(const int* __restrict__ ops,
                                               const float* __restrict__ cIn,
                                               const float* __restrict__ att_init) {
    int b = blockIdx.y;
    int ag = threadIdx.x;
    int ny = threadIdx.y;
    int tid = ny * 16 + ag;
    __shared__ float s_Ms[4096], s_meta[768], s_ai[64];
    __shared__ float s_ti[8][64], s_pr[8][16];
    __shared__ int s_opf[12];
    for (int i = tid; i < 4096; i += 128) s_Ms[i] = g_Msum[b * 4096 + i];
    for (int i = tid; i < 768; i += 128) s_meta[i] = g_meta[b * 768 + i];
    if (tid < 64) s_ai[tid] = att_init[tid];
    if (tid < 12) s_opf[tid] = ops[b * L_ + tid];
    int base = blockIdx.x * 32;
    for (int g4 = 0; g4 < 4; g4++) {
        int n0 = base + g4 * 8;
        __syncthreads();
        for (int i = tid; i < 512; i += 128) {
            int r = i >> 6, e = i & 63;
            int n = n0 + r;
            const float* row = (n < C_) ? cIn + (size_t)n * 64
                                        : g_objIn + (size_t)(b * O_ + n - C_) * 64;
            s_ti[r][e] = row[e];
        }
        {
            int r = tid >> 4, c = tid & 15;
            s_pr[r][c] = g_proj[(size_t)(b * N_ + n0 + r) * 16 + c];
        }
        __syncthreads();
        int n = n0 + ny;
        int a0 = ag * 4;
        float v0 = s_ai[a0], v1 = s_ai[a0 + 1], v2 = s_ai[a0 + 2], v3 = s_ai[a0 + 3];
#pragma unroll
        for (int s = 0; s < 12; s++)
            if (s_opf[s] == 1) {
                float pp = s_pr[ny][s];
                v0 += pp * s_meta[s * 64 + a0];
                v1 += pp * s_meta[s * 64 + a0 + 1];
                v2 += pp * s_meta[s * 64 + a0 + 2];
                v3 += pp * s_meta[s * 64 + a0 + 3];
            }
        const float4* Ms4 = (const float4*)s_Ms;
#pragma unroll
        for (int e = 0; e < 64; e++) {
            float ti = s_ti[ny][e];
            float4 m = Ms4[e * 16 + ag];
            v0 += ti * m.x; v1 += ti * m.y; v2 += ti * m.z; v3 += ti * m.w;
        }
        float sq = v0 * v0 + v1 * v1 + v2 * v2 + v3 * v3;
#pragma unroll
        for (int o = 8; o > 0; o >>= 1) sq += __shfl_xor_sync(0xffffffffu, sq, o);
        if (ag == 0) {
            float ol = sq * (1.0f / 64.0f);
            g_ol[b * N_ + n] = ol;
            atomicMax(&g_olmax[b], __float_as_int(ol));  // ol >= 0
        }
    }
}

// ---------------- 8: softmax ----------------------------------------------------
__global__ void __launch_bounds__(1024) k_soft(float* __restrict__ out) {
    int b = blockIdx.x;
    int tid = threadIdx.x;
    __shared__ float s_red[1024];
    float mx = __int_as_float(g_olmax[b]);
    float lsum = 0.f;
    for (int n = tid; n < N_; n += 1024) lsum += expf(g_ol[b * N_ + n] - mx);
    s_red[tid] = lsum;
    __syncthreads();
    for (int s = 512; s > 0; s >>= 1) {
        if (tid < s) s_red[tid] += s_red[tid + s];
        __syncthreads();
    }
    float lse = logf(s_red[0]) + mx;
    for (int n = tid; n < N_; n += 1024) out[b * N_ + n] = g_ol[b * N_ + n] - lse;
}

// ---------------- launch --------------------------------------------------------
extern "C" void kernel_launch(void* const* d_in, const int* in_sizes, int n_in,
                              void* d_out, int out_size) {
    const float* class_embIn   = (const float*)d_in[0];
    const float* class_embOut  = (const float*)d_in[1];
    const float* attr_embIn    = (const float*)d_in[2];
    const float* attr_embOut   = (const float*)d_in[3];
    const float* concept_embIn = (const float*)d_in[4];
    const float* concept_embOut= (const float*)d_in[5];
    const float* meta_init     = (const float*)d_in[6];
    const float* attention_init= (const float*)d_in[8];
    const float* axon_w1       = (const float*)d_in[9];
    const float* axon_b1       = (const float*)d_in[10];
    const float* axon_w2       = (const float*)d_in[11];
    const float* axon_b2       = (const float*)d_in[12];
    const float* meta_w1       = (const float*)d_in[13];
    const float* meta_b1       = (const float*)d_in[14];
    const float* meta_w2       = (const float*)d_in[15];
    const float* meta_b2       = (const float*)d_in[16];
    const int*   program_ops   = (const int*)d_in[17];
    const int*   program_args  = (const int*)d_in[18];
    const int*   gt_classes    = (const int*)d_in[19];
    const int*   gt_attributes = (const int*)d_in[20];
    float* out = (float*)d_out;

    cudaFuncSetAttribute(k_meta, cudaFuncAttributeMaxDynamicSharedMemorySize,
                         49152 * (int)sizeof(float));
    cudaFuncSetAttribute(k_D, cudaFuncAttributeMaxDynamicSharedMemorySize, KD_SMEM);

    k_pre<<<345, 256>>>(class_embIn, class_embOut, attr_embIn, attr_embOut,   // 1
                        gt_classes, gt_attributes, axon_w1, concept_embOut,
                        program_args);
    k_meta<<<B_, 512, 49152 * sizeof(float)>>>(meta_init, meta_w1, meta_b1,   // 2
                                               meta_w2, meta_b2, program_ops);
    k_proj<<<dim3(NTILES, B_), 256>>>(concept_embOut, concept_embIn);         // 3
    k_D<<<dim3(NSPLIT, L_, B_), 256, KD_SMEM>>>(program_ops, axon_w1, axon_b1); // 4
    k_E<<<dim3(L_, B_), 256>>>(program_ops, axon_w2);                         // 5
    k_rec<<<B_, 1024>>>(program_ops, axon_b2, attention_init);                // 6
    k_final<<<dim3(N_ / 32, B_), dim3(16, 8)>>>(program_ops, concept_embIn,   // 7
                                                attention_init);
    k_soft<<<B_, 1024>>>(out);                                                // 8
}